// round 7
// baseline (speedup 1.0000x reference)
#include <cuda_runtime.h>
#include <cuda_bf16.h>
#include <stdint.h>

// ============================================================================
// Problem constants / layout
// ============================================================================
#define D 128
#define TILE_M 128

#define ROW_BYTES  272            // padded bf16 row (136 bf16): stride%128=16 -> ldmatrix conflict-free
#define STAGE_STRIDE 132          // fp32 stage row stride

// SMEM layout (bytes): A tiles only; W comes from global fragment arrays.
#define OFF_A_HI   0              // 128 x 272B = 34816
#define OFF_A_LO   34816
#define OFF_BIAS   69632          // 128 floats
#define SMEM_TOTAL 70144
// stage buffer (fp32 128 x 132 = 67584 B) reuses [0, 67584) after MMA.

// ============================================================================
// PTX helpers (base-ISA only: ldmatrix / mma.sync — compiles at plain sm_103)
// ============================================================================
__device__ __forceinline__ uint32_t smem_to_u32(const void* p) {
    uint32_t a;
    asm("{ .reg .u64 t; cvta.to.shared.u64 t, %1; cvt.u32.u64 %0, t; }" : "=r"(a) : "l"(p));
    return a;
}

#define LDSM4(r, addr) \
    asm volatile("ldmatrix.sync.aligned.m8n8.x4.shared.b16 {%0,%1,%2,%3}, [%4];" \
        : "=r"((r)[0]), "=r"((r)[1]), "=r"((r)[2]), "=r"((r)[3]) : "r"(addr))

#define MMA_BF16(c, a, b0, b1) \
    asm volatile("mma.sync.aligned.m16n8k16.row.col.f32.bf16.bf16.f32 " \
        "{%0,%1,%2,%3},{%4,%5,%6,%7},{%8,%9},{%0,%1,%2,%3};" \
        : "+f"((c)[0]), "+f"((c)[1]), "+f"((c)[2]), "+f"((c)[3]) \
        : "r"((a)[0]), "r"((a)[1]), "r"((a)[2]), "r"((a)[3]), \
          "r"(b0), "r"(b1))

// ============================================================================
// W in B-fragment order: [kstep(8)][n8tile(16)][lane(32)] -> uint2 {b0, b1}
// ============================================================================
__device__ uint2 g_Wf_hi[8 * 16 * 32];  // 32 KB
__device__ uint2 g_Wf_lo[8 * 16 * 32];  // 32 KB

// fp32 -> (bf16 hi, bf16 lo) split, two values packed per uint32
__device__ __forceinline__ void split2(float x0, float x1, uint32_t& hi, uint32_t& lo) {
    __nv_bfloat16 h0 = __float2bfloat16_rn(x0);
    __nv_bfloat16 h1 = __float2bfloat16_rn(x1);
    __nv_bfloat16 l0 = __float2bfloat16_rn(x0 - __bfloat162float(h0));
    __nv_bfloat16 l1 = __float2bfloat16_rn(x1 - __bfloat162float(h1));
    hi = (uint32_t)__bfloat16_as_ushort(h0) | ((uint32_t)__bfloat16_as_ushort(h1) << 16);
    lo = (uint32_t)__bfloat16_as_ushort(l0) | ((uint32_t)__bfloat16_as_ushort(l1) << 16);
}

// ============================================================================
// Kernel 0 (merged prep): init out to -inf AND pack W into fragment order.
// ============================================================================
__global__ void prep_kernel(int4* __restrict__ out, int n4, const float* __restrict__ W) {
    const int init_blocks = (n4 + 255) / 256;
    if ((int)blockIdx.x < init_blocks) {
        int i = blockIdx.x * 256 + threadIdx.x;
        if (i < n4) {
            const int m = 0xff800000;  // -inf
            out[i] = make_int4(m, m, m, m);
        }
    } else {
        int i = (blockIdx.x - init_blocks) * 256 + threadIdx.x;  // 0 .. 4095
        if (i < 8 * 16 * 32) {
            int lane = i & 31;
            int n8t  = (i >> 5) & 15;
            int kst  = i >> 9;
            int n  = n8t * 8 + (lane >> 2);
            int k0 = kst * 16 + (lane & 3) * 2;
            const float* Wr = W + (size_t)n * D;
            uint32_t h0, l0, h1, l1;
            split2(Wr[k0],     Wr[k0 + 1], h0, l0);
            split2(Wr[k0 + 8], Wr[k0 + 9], h1, l1);
            g_Wf_hi[i] = make_uint2(h0, h1);
            g_Wf_lo[i] = make_uint2(l0, l1);
        }
    }
}

// ============================================================================
// Kernel 1: fused GEMM (mma.sync bf16 x3 split) + bias + relu + segment-max
// ============================================================================
__global__ __launch_bounds__(256, 2) void fused_kernel(
    const float* __restrict__ src,
    const float* __restrict__ b,
    const int* __restrict__ dst_idx,   // int32 (JAX x64-disabled downcasts int64)
    int* __restrict__ out,
    int E, int N)
{
    extern __shared__ __align__(16) char smem[];
    float* bias_s = reinterpret_cast<float*>(smem + OFF_BIAS);

    const int tid  = threadIdx.x;
    const int wid  = tid >> 5;
    const int lane = tid & 31;

    const int m_base = (wid & 3) * 32;   // warp M tile (rows)
    const int n_base = (wid >> 2) * 64;  // warp N tile (cols)
    const int nb8    = n_base >> 3;      // first n8 tile index for this warp

    const int tile_base = blockIdx.x * TILE_M;
    const int rem = min(TILE_M, E - tile_base);

    // ---- bias -> smem ----
    if (tid < D) bias_s[tid] = b[tid];

    // ---- convert src tile fp32 -> bf16 hi/lo into padded SMEM ----
    {
        const float4* srcT = reinterpret_cast<const float4*>(src + (size_t)tile_base * D);
        #pragma unroll
        for (int i = tid; i < TILE_M * D / 4; i += 256) {  // 4096 float4
            int row = i >> 5;
            int col = (i & 31) * 4;
            float4 x;
            if (row < rem) x = __ldcs(&srcT[i]);  // streaming: don't evict W frags
            else x = make_float4(0.f, 0.f, 0.f, 0.f);
            uint32_t h01, l01, h23, l23;
            split2(x.x, x.y, h01, l01);
            split2(x.z, x.w, h23, l23);
            size_t soff = (size_t)row * ROW_BYTES + (size_t)col * 2;
            *reinterpret_cast<uint2*>(smem + OFF_A_HI + soff) = make_uint2(h01, h23);
            *reinterpret_cast<uint2*>(smem + OFF_A_LO + soff) = make_uint2(l01, l23);
        }
    }

    __syncthreads();

    // ---- ldmatrix base addresses for A ----
    const uint32_t sb = smem_to_u32(smem);
    uint32_t aHi = sb + OFF_A_HI + (uint32_t)(m_base + (lane & 15)) * ROW_BYTES + (uint32_t)(lane >> 4) * 16;
    uint32_t aLo = aHi + (OFF_A_LO - OFF_A_HI);

    float acc[2][8][4];
    #pragma unroll
    for (int mt = 0; mt < 2; mt++)
        #pragma unroll
        for (int nt = 0; nt < 8; nt++)
            #pragma unroll
            for (int c = 0; c < 4; c++) acc[mt][nt][c] = 0.f;

    // ---- mainloop: K=128 in 8 k16 steps; B fragments streamed from global (L1-hot) ----
    #pragma unroll
    for (int k = 0; k < 8; k++) {
        uint32_t ah[2][4], al[2][4];
        #pragma unroll
        for (int mt = 0; mt < 2; mt++) {
            LDSM4(ah[mt], aHi + (uint32_t)mt * 16 * ROW_BYTES + (uint32_t)k * 32);
            LDSM4(al[mt], aLo + (uint32_t)mt * 16 * ROW_BYTES + (uint32_t)k * 32);
        }
        const int fbase = (k * 16 + nb8) * 32 + lane;
        #pragma unroll
        for (int nt = 0; nt < 8; nt++) {
            const uint2 Bh = g_Wf_hi[fbase + nt * 32];
            const uint2 Bl = g_Wf_lo[fbase + nt * 32];
            #pragma unroll
            for (int mt = 0; mt < 2; mt++) {
                MMA_BF16(acc[mt][nt], ah[mt], Bh.x, Bh.y);
                MMA_BF16(acc[mt][nt], al[mt], Bh.x, Bh.y);
                MMA_BF16(acc[mt][nt], ah[mt], Bl.x, Bl.y);
            }
        }
    }

    __syncthreads();  // all warps done reading A smem -> safe to reuse as stage

    // ---- epilogue: bias + relu -> fp32 stage in SMEM ----
    {
        float* stage = reinterpret_cast<float*>(smem);
        const int r0 = m_base + (lane >> 2);
        const int cb = 2 * (lane & 3);
        #pragma unroll
        for (int mt = 0; mt < 2; mt++) {
            #pragma unroll
            for (int nt = 0; nt < 8; nt++) {
                int col = n_base + nt * 8 + cb;
                float bv0 = bias_s[col], bv1 = bias_s[col + 1];
                int rr = r0 + mt * 16;
                stage[rr * STAGE_STRIDE + col]           = fmaxf(acc[mt][nt][0] + bv0, 0.f);
                stage[rr * STAGE_STRIDE + col + 1]       = fmaxf(acc[mt][nt][1] + bv1, 0.f);
                stage[(rr + 8) * STAGE_STRIDE + col]     = fmaxf(acc[mt][nt][2] + bv0, 0.f);
                stage[(rr + 8) * STAGE_STRIDE + col + 1] = fmaxf(acc[mt][nt][3] + bv1, 0.f);
            }
        }
    }
    __syncthreads();

    // ---- scatter: BATCHED monotonic read-filter + predicated atomicMax ----
    // out only increases (atomicMax is monotone) => a racy pre-read showing
    // cur >= mine proves the atomic is a no-op; stale reads are only LOWER
    // than truth => never skip wrongly. Unlike R4, reads are BATCHED 4 rows
    // at a time (4 independent LDG.128, MLP=4) instead of serial read->atomic,
    // so the L2 latency is pipelined. Expected ~78% of atomic lanes skipped.
    {
        const float* stage = reinterpret_cast<const float*>(smem);
        const int c0 = 4 * lane;  // lane owns cols [4*lane, 4*lane+4)
        #pragma unroll
        for (int j0 = 0; j0 < 16; j0 += 4) {   // rows rr = wid + 8*(j0..j0+3)
            float4 mine[4], cur[4];
            int*  op[4];
            bool  ok[4];
            // phase A: issue all loads (independent -> overlapped)
            #pragma unroll
            for (int u = 0; u < 4; u++) {
                int rr = wid + (j0 + u) * 8;
                int dst = (rr < rem) ? dst_idx[tile_base + rr] : -1;
                ok[u] = ((unsigned)dst < (unsigned)N);
                if (ok[u]) {
                    op[u] = out + (size_t)dst * D + c0;
                    cur[u] = __ldcg(reinterpret_cast<const float4*>(op[u]));
                    mine[u] = *reinterpret_cast<const float4*>(&stage[rr * STAGE_STRIDE + c0]);
                }
            }
            // phase B: predicated fire-and-forget atomics
            #pragma unroll
            for (int u = 0; u < 4; u++) {
                if (!ok[u]) continue;
                if (mine[u].x > cur[u].x) atomicMax(op[u] + 0, __float_as_int(mine[u].x));
                if (mine[u].y > cur[u].y) atomicMax(op[u] + 1, __float_as_int(mine[u].y));
                if (mine[u].z > cur[u].z) atomicMax(op[u] + 2, __float_as_int(mine[u].z));
                if (mine[u].w > cur[u].w) atomicMax(op[u] + 3, __float_as_int(mine[u].w));
            }
        }
    }
}

// ============================================================================
// Launch
// ============================================================================
extern "C" void kernel_launch(void* const* d_in, const int* in_sizes, int n_in,
                              void* d_out, int out_size) {
    const float* src     = (const float*)d_in[0];
    const float* W       = (const float*)d_in[1];
    const float* b       = (const float*)d_in[2];
    const int*   dst     = (const int*)d_in[3];   // int32 on device

    const int E = in_sizes[0] / D;
    const int N = out_size / D;
    const int tiles = (E + TILE_M - 1) / TILE_M;

    // 0: merged prep (init out to -inf + pack W fragments)
    int n4 = out_size / 4;
    int init_blocks = (n4 + 255) / 256;
    int frag_blocks = (8 * 16 * 32 + 255) / 256;
    prep_kernel<<<init_blocks + frag_blocks, 256>>>((int4*)d_out, n4, W);

    // 1: fused GEMM + filtered scatter-max
    cudaFuncSetAttribute(fused_kernel, cudaFuncAttributeMaxDynamicSharedMemorySize,
                         SMEM_TOTAL);
    fused_kernel<<<tiles, 256, SMEM_TOTAL>>>(src, b, dst, (int*)d_out, E, N);
}

// round 8
// speedup vs baseline: 1.1385x; 1.1385x over previous
#include <cuda_runtime.h>
#include <cuda_bf16.h>
#include <stdint.h>

// ============================================================================
// Problem constants / layout
// ============================================================================
#define D 128
#define TILE_M 128
#define E_MAX 640000
#define N_MAX 40000

#define ROW_BYTES  272            // padded bf16 row: stride%128=16 -> ldmatrix conflict-free
#define STAGE_STRIDE 132          // fp32 stage row stride

// SMEM layout (bytes): A tiles; W comes from global fragment arrays.
#define OFF_A_HI   0              // 128 x 272B = 34816
#define OFF_A_LO   34816
#define OFF_BIAS   69632          // 128 floats (512B)
#define OFF_PERM   70144          // 128 ints   (512B)
#define OFF_DST    70656          // 128 ints   (512B)
#define SMEM_TOTAL 71168
// stage buffer (fp32 128 x 132 = 67584 B) reuses [0, 67584) after MMA.

// ============================================================================
// PTX helpers (base ISA only)
// ============================================================================
__device__ __forceinline__ uint32_t smem_to_u32(const void* p) {
    uint32_t a;
    asm("{ .reg .u64 t; cvta.to.shared.u64 t, %1; cvt.u32.u64 %0, t; }" : "=r"(a) : "l"(p));
    return a;
}

#define LDSM4(r, addr) \
    asm volatile("ldmatrix.sync.aligned.m8n8.x4.shared.b16 {%0,%1,%2,%3}, [%4];" \
        : "=r"((r)[0]), "=r"((r)[1]), "=r"((r)[2]), "=r"((r)[3]) : "r"(addr))

#define MMA_BF16(c, a, b0, b1) \
    asm volatile("mma.sync.aligned.m16n8k16.row.col.f32.bf16.bf16.f32 " \
        "{%0,%1,%2,%3},{%4,%5,%6,%7},{%8,%9},{%0,%1,%2,%3};" \
        : "+f"((c)[0]), "+f"((c)[1]), "+f"((c)[2]), "+f"((c)[3]) \
        : "r"((a)[0]), "r"((a)[1]), "r"((a)[2]), "r"((a)[3]), \
          "r"(b0), "r"(b1))

// ============================================================================
// Device scratch
// ============================================================================
__device__ uint2 g_Wf_hi[8 * 16 * 32];  // W B-fragments hi (32 KB)
__device__ uint2 g_Wf_lo[8 * 16 * 32];  // W B-fragments lo (32 KB)
__device__ int g_count[N_MAX];
__device__ int g_offset[N_MAX];
__device__ int g_cursor[N_MAX];
__device__ int g_perm[E_MAX + TILE_M];
__device__ int g_dst_sorted[E_MAX + TILE_M];

// fp32 -> (bf16 hi, bf16 lo) split, two values packed per uint32
__device__ __forceinline__ void split2(float x0, float x1, uint32_t& hi, uint32_t& lo) {
    __nv_bfloat16 h0 = __float2bfloat16_rn(x0);
    __nv_bfloat16 h1 = __float2bfloat16_rn(x1);
    __nv_bfloat16 l0 = __float2bfloat16_rn(x0 - __bfloat162float(h0));
    __nv_bfloat16 l1 = __float2bfloat16_rn(x1 - __bfloat162float(h1));
    hi = (uint32_t)__bfloat16_as_ushort(h0) | ((uint32_t)__bfloat16_as_ushort(h1) << 16);
    lo = (uint32_t)__bfloat16_as_ushort(l0) | ((uint32_t)__bfloat16_as_ushort(l1) << 16);
}

// ============================================================================
// Kernel 0: init out to -inf, pack W fragments, zero counters
// ============================================================================
__global__ void prep_kernel(int4* __restrict__ out, int n4, const float* __restrict__ W, int N) {
    const int init_blocks = (n4 + 255) / 256;
    const int frag_blocks = (8 * 16 * 32 + 255) / 256;
    int bx = blockIdx.x;
    if (bx < init_blocks) {
        int i = bx * 256 + threadIdx.x;
        if (i < n4) {
            const int m = 0xff800000;  // -inf
            out[i] = make_int4(m, m, m, m);
        }
    } else if (bx < init_blocks + frag_blocks) {
        int i = (bx - init_blocks) * 256 + threadIdx.x;  // 0 .. 4095
        if (i < 8 * 16 * 32) {
            int lane = i & 31;
            int n8t  = (i >> 5) & 15;
            int kst  = i >> 9;
            int n  = n8t * 8 + (lane >> 2);
            int k0 = kst * 16 + (lane & 3) * 2;
            const float* Wr = W + (size_t)n * D;
            uint32_t h0, l0, h1, l1;
            split2(Wr[k0],     Wr[k0 + 1], h0, l0);
            split2(Wr[k0 + 8], Wr[k0 + 9], h1, l1);
            g_Wf_hi[i] = make_uint2(h0, h1);
            g_Wf_lo[i] = make_uint2(l0, l1);
        }
    } else {
        int i = (bx - init_blocks - frag_blocks) * 256 + threadIdx.x;
        if (i < N) { g_count[i] = 0; g_cursor[i] = 0; }
    }
}

// ============================================================================
// Kernel 1: histogram of dst
// ============================================================================
__global__ void hist_kernel(const int* __restrict__ dst_idx, int E, int N) {
    int i = blockIdx.x * blockDim.x + threadIdx.x;
    if (i < E) {
        int d = dst_idx[i];
        if ((unsigned)d < (unsigned)N) atomicAdd(&g_count[d], 1);
    }
}

// ============================================================================
// Kernel 2: single-CTA exclusive scan of g_count -> g_offset
// ============================================================================
__global__ __launch_bounds__(1024, 1) void scan_kernel(int N) {
    __shared__ int sums[1024];
    const int t = threadIdx.x;
    const int CH = (N + 1023) >> 10;
    const int base = t * CH;
    int s = 0;
    for (int j = 0; j < CH; j++) {
        int idx = base + j;
        if (idx < N) s += g_count[idx];
    }
    sums[t] = s;
    __syncthreads();
    // inclusive Hillis-Steele scan over 1024 partials
    for (int off = 1; off < 1024; off <<= 1) {
        int v = (t >= off) ? sums[t - off] : 0;
        __syncthreads();
        sums[t] += v;
        __syncthreads();
    }
    int run = sums[t] - s;  // exclusive prefix for this chunk
    for (int j = 0; j < CH; j++) {
        int idx = base + j;
        if (idx < N) { g_offset[idx] = run; run += g_count[idx]; }
    }
}

// ============================================================================
// Kernel 3: scatter edges into dst-sorted order
// ============================================================================
__global__ void scatter_perm_kernel(const int* __restrict__ dst_idx, int E, int N) {
    int i = blockIdx.x * blockDim.x + threadIdx.x;
    if (i < E) {
        int d = dst_idx[i];
        if ((unsigned)d < (unsigned)N) {
            int pos = g_offset[d] + atomicAdd(&g_cursor[d], 1);
            g_perm[pos] = i;
            g_dst_sorted[pos] = d;
        }
    }
    // pad tail of last tile
    int pad = E + i;
    if (i < TILE_M && pad < E_MAX + TILE_M) { /* no-op: guarded by rem in fused */ }
}

// ============================================================================
// Kernel 4: fused GEMM (mma.sync bf16 x3 split, dst-sorted gather)
//           + bias + relu + segmented max flush
// ============================================================================
__global__ __launch_bounds__(256, 2) void fused_kernel(
    const float* __restrict__ src,
    const float* __restrict__ b,
    int* __restrict__ out,
    int E, int N)
{
    extern __shared__ __align__(16) char smem[];
    float* bias_s = reinterpret_cast<float*>(smem + OFF_BIAS);
    int*   perm_s = reinterpret_cast<int*>(smem + OFF_PERM);
    int*   dst_s  = reinterpret_cast<int*>(smem + OFF_DST);

    const int tid  = threadIdx.x;
    const int wid  = tid >> 5;
    const int lane = tid & 31;

    const int m_base = (wid & 3) * 32;   // warp M tile (rows)
    const int n_base = (wid >> 2) * 64;  // warp N tile (cols)
    const int nb8    = n_base >> 3;

    const int tile_base = blockIdx.x * TILE_M;
    const int rem = min(TILE_M, E - tile_base);

    // ---- bias + perm + sorted-dst slices -> smem ----
    if (tid < D) bias_s[tid] = b[tid];
    if (tid < TILE_M) {
        int p = tile_base + tid;
        perm_s[tid] = (tid < rem) ? g_perm[p] : 0;
        dst_s[tid]  = (tid < rem) ? g_dst_sorted[p] : -1;
    }
    __syncthreads();

    // ---- convert gathered src rows fp32 -> bf16 hi/lo into padded SMEM ----
    {
        const float4* srcT = reinterpret_cast<const float4*>(src);
        #pragma unroll
        for (int i = tid; i < TILE_M * D / 4; i += 256) {  // 4096 float4
            int row = i >> 5;
            int col4 = i & 31;
            float4 x;
            if (row < rem) x = __ldcs(&srcT[(size_t)perm_s[row] * 32 + col4]);
            else x = make_float4(0.f, 0.f, 0.f, 0.f);
            uint32_t h01, l01, h23, l23;
            split2(x.x, x.y, h01, l01);
            split2(x.z, x.w, h23, l23);
            size_t soff = (size_t)row * ROW_BYTES + (size_t)col4 * 8;
            *reinterpret_cast<uint2*>(smem + OFF_A_HI + soff) = make_uint2(h01, h23);
            *reinterpret_cast<uint2*>(smem + OFF_A_LO + soff) = make_uint2(l01, l23);
        }
    }

    __syncthreads();

    // ---- ldmatrix base addresses for A ----
    const uint32_t sb = smem_to_u32(smem);
    uint32_t aHi = sb + OFF_A_HI + (uint32_t)(m_base + (lane & 15)) * ROW_BYTES + (uint32_t)(lane >> 4) * 16;
    uint32_t aLo = aHi + (OFF_A_LO - OFF_A_HI);

    float acc[2][8][4];
    #pragma unroll
    for (int mt = 0; mt < 2; mt++)
        #pragma unroll
        for (int nt = 0; nt < 8; nt++)
            #pragma unroll
            for (int c = 0; c < 4; c++) acc[mt][nt][c] = 0.f;

    // ---- mainloop: K=128 in 8 k16 steps; B fragments from global (L1-hot) ----
    #pragma unroll
    for (int k = 0; k < 8; k++) {
        uint32_t ah[2][4], al[2][4];
        #pragma unroll
        for (int mt = 0; mt < 2; mt++) {
            LDSM4(ah[mt], aHi + (uint32_t)mt * 16 * ROW_BYTES + (uint32_t)k * 32);
            LDSM4(al[mt], aLo + (uint32_t)mt * 16 * ROW_BYTES + (uint32_t)k * 32);
        }
        const int fbase = (k * 16 + nb8) * 32 + lane;
        #pragma unroll
        for (int nt = 0; nt < 8; nt++) {
            const uint2 Bh = g_Wf_hi[fbase + nt * 32];
            const uint2 Bl = g_Wf_lo[fbase + nt * 32];
            #pragma unroll
            for (int mt = 0; mt < 2; mt++) {
                MMA_BF16(acc[mt][nt], ah[mt], Bh.x, Bh.y);
                MMA_BF16(acc[mt][nt], al[mt], Bh.x, Bh.y);
                MMA_BF16(acc[mt][nt], ah[mt], Bl.x, Bl.y);
            }
        }
    }

    __syncthreads();  // all warps done with A smem -> reuse as stage

    // ---- epilogue: bias + relu -> fp32 stage in SMEM ----
    {
        float* stage = reinterpret_cast<float*>(smem);
        const int r0 = m_base + (lane >> 2);
        const int cb = 2 * (lane & 3);
        #pragma unroll
        for (int mt = 0; mt < 2; mt++) {
            #pragma unroll
            for (int nt = 0; nt < 8; nt++) {
                int col = n_base + nt * 8 + cb;
                float bv0 = bias_s[col], bv1 = bias_s[col + 1];
                int rr = r0 + mt * 16;
                stage[rr * STAGE_STRIDE + col]           = fmaxf(acc[mt][nt][0] + bv0, 0.f);
                stage[rr * STAGE_STRIDE + col + 1]       = fmaxf(acc[mt][nt][1] + bv1, 0.f);
                stage[(rr + 8) * STAGE_STRIDE + col]     = fmaxf(acc[mt][nt][2] + bv0, 0.f);
                stage[(rr + 8) * STAGE_STRIDE + col + 1] = fmaxf(acc[mt][nt][3] + bv1, 0.f);
            }
        }
    }
    __syncthreads();

    // ---- segmented max flush: rows are dst-sorted; warp scans 16 contiguous
    //      rows keeping a running max per lane (4 cols), flushing one atomic
    //      batch per distinct dst (~2-3 per warp instead of 16). ----
    {
        const float* stage = reinterpret_cast<const float*>(smem);
        const int c0 = 4 * lane;  // lane owns cols [4*lane, 4*lane+4)
        const int r_begin = wid * 16;
        const int r_end   = min(r_begin + 16, rem);

        float4 run = make_float4(0.f, 0.f, 0.f, 0.f);
        int cur = -1;
        for (int rr = r_begin; rr < r_end; rr++) {
            int d = dst_s[rr];
            float4 mine = *reinterpret_cast<const float4*>(&stage[rr * STAGE_STRIDE + c0]);
            if (d != cur) {
                if (cur >= 0) {
                    int* op = out + (size_t)cur * D + c0;
                    atomicMax(op + 0, __float_as_int(run.x));
                    atomicMax(op + 1, __float_as_int(run.y));
                    atomicMax(op + 2, __float_as_int(run.z));
                    atomicMax(op + 3, __float_as_int(run.w));
                }
                cur = d;
                run = mine;
            } else {
                run.x = fmaxf(run.x, mine.x);
                run.y = fmaxf(run.y, mine.y);
                run.z = fmaxf(run.z, mine.z);
                run.w = fmaxf(run.w, mine.w);
            }
        }
        if (cur >= 0) {
            int* op = out + (size_t)cur * D + c0;
            atomicMax(op + 0, __float_as_int(run.x));
            atomicMax(op + 1, __float_as_int(run.y));
            atomicMax(op + 2, __float_as_int(run.z));
            atomicMax(op + 3, __float_as_int(run.w));
        }
    }
}

// ============================================================================
// Launch
// ============================================================================
extern "C" void kernel_launch(void* const* d_in, const int* in_sizes, int n_in,
                              void* d_out, int out_size) {
    const float* src     = (const float*)d_in[0];
    const float* W       = (const float*)d_in[1];
    const float* b       = (const float*)d_in[2];
    const int*   dst     = (const int*)d_in[3];   // int32 on device

    const int E = in_sizes[0] / D;
    const int N = out_size / D;
    const int tiles = (E + TILE_M - 1) / TILE_M;

    // 0: init out + pack W frags + zero counters
    int n4 = out_size / 4;
    int init_blocks = (n4 + 255) / 256;
    int frag_blocks = (8 * 16 * 32 + 255) / 256;
    int zero_blocks = (N + 255) / 256;
    prep_kernel<<<init_blocks + frag_blocks + zero_blocks, 256>>>((int4*)d_out, n4, W, N);

    // 1-3: counting sort of edges by dst
    hist_kernel<<<(E + 255) / 256, 256>>>(dst, E, N);
    scan_kernel<<<1, 1024>>>(N);
    scatter_perm_kernel<<<(E + 255) / 256, 256>>>(dst, E, N);

    // 4: fused GEMM (gathered) + segmented scatter-max
    cudaFuncSetAttribute(fused_kernel, cudaFuncAttributeMaxDynamicSharedMemorySize,
                         SMEM_TOTAL);
    fused_kernel<<<tiles, 256, SMEM_TOTAL>>>(src, b, (int*)d_out, E, N);
}

// round 9
// speedup vs baseline: 1.4910x; 1.3097x over previous
#include <cuda_runtime.h>
#include <cuda_bf16.h>
#include <stdint.h>

// ============================================================================
// Problem constants / layout
// ============================================================================
#define D 128
#define TILE_M 64                 // edges per CTA (full 128 cols per CTA)

#define ROW_BYTES  272            // padded bf16 row: stride%128=16 -> ldmatrix conflict-free
#define STAGE_STRIDE 132          // fp32 stage row stride

// SMEM layout (bytes): A tiles only; W streams from global fragment table.
#define OFF_A_HI   0              // 64 x 272B = 17408
#define OFF_A_LO   17408
#define OFF_BIAS   34816          // 128 floats
#define SMEM_TOTAL 35328
// stage buffer (fp32 64 x 132 = 33792 B) reuses [0, 33792) after MMA.

// ============================================================================
// PTX helpers (base ISA only: ldmatrix / mma.sync)
// ============================================================================
__device__ __forceinline__ uint32_t smem_to_u32(const void* p) {
    uint32_t a;
    asm("{ .reg .u64 t; cvta.to.shared.u64 t, %1; cvt.u32.u64 %0, t; }" : "=r"(a) : "l"(p));
    return a;
}

#define LDSM4(r, addr) \
    asm volatile("ldmatrix.sync.aligned.m8n8.x4.shared.b16 {%0,%1,%2,%3}, [%4];" \
        : "=r"((r)[0]), "=r"((r)[1]), "=r"((r)[2]), "=r"((r)[3]) : "r"(addr))

#define MMA_BF16(c, a, b0, b1) \
    asm volatile("mma.sync.aligned.m16n8k16.row.col.f32.bf16.bf16.f32 " \
        "{%0,%1,%2,%3},{%4,%5,%6,%7},{%8,%9},{%0,%1,%2,%3};" \
        : "+f"((c)[0]), "+f"((c)[1]), "+f"((c)[2]), "+f"((c)[3]) \
        : "r"((a)[0]), "r"((a)[1]), "r"((a)[2]), "r"((a)[3]), \
          "r"(b0), "r"(b1))

// ============================================================================
// W in B-fragment order: [kstep(8)][n8tile(16)][lane(32)] -> uint2 {b0, b1}
// ============================================================================
__device__ uint2 g_Wf_hi[8 * 16 * 32];  // 32 KB
__device__ uint2 g_Wf_lo[8 * 16 * 32];  // 32 KB

// fp32 -> (bf16 hi, bf16 lo) split, two values packed per uint32
__device__ __forceinline__ void split2(float x0, float x1, uint32_t& hi, uint32_t& lo) {
    __nv_bfloat16 h0 = __float2bfloat16_rn(x0);
    __nv_bfloat16 h1 = __float2bfloat16_rn(x1);
    __nv_bfloat16 l0 = __float2bfloat16_rn(x0 - __bfloat162float(h0));
    __nv_bfloat16 l1 = __float2bfloat16_rn(x1 - __bfloat162float(h1));
    hi = (uint32_t)__bfloat16_as_ushort(h0) | ((uint32_t)__bfloat16_as_ushort(h1) << 16);
    lo = (uint32_t)__bfloat16_as_ushort(l0) | ((uint32_t)__bfloat16_as_ushort(l1) << 16);
}

// ============================================================================
// Kernel 0 (merged prep): init out to -inf AND pack W into fragment order.
// ============================================================================
__global__ void prep_kernel(int4* __restrict__ out, int n4, const float* __restrict__ W) {
    const int init_blocks = (n4 + 255) / 256;
    if ((int)blockIdx.x < init_blocks) {
        int i = blockIdx.x * 256 + threadIdx.x;
        if (i < n4) {
            const int m = 0xff800000;  // -inf
            out[i] = make_int4(m, m, m, m);
        }
    } else {
        int i = (blockIdx.x - init_blocks) * 256 + threadIdx.x;  // 0 .. 4095
        if (i < 8 * 16 * 32) {
            int lane = i & 31;
            int n8t  = (i >> 5) & 15;
            int kst  = i >> 9;
            int n  = n8t * 8 + (lane >> 2);
            int k0 = kst * 16 + (lane & 3) * 2;
            const float* Wr = W + (size_t)n * D;
            uint32_t h0, l0, h1, l1;
            split2(Wr[k0],     Wr[k0 + 1], h0, l0);
            split2(Wr[k0 + 8], Wr[k0 + 9], h1, l1);
            g_Wf_hi[i] = make_uint2(h0, h1);
            g_Wf_lo[i] = make_uint2(l0, l1);
        }
    }
}

// ============================================================================
// Kernel 1: fused GEMM (mma.sync bf16 x3 split) + bias + relu + segment-max
// CTA tile: 64 edges x 128 cols. Warp tile 32x32. 3 CTAs/SM.
// ============================================================================
__global__ __launch_bounds__(256, 3) void fused_kernel(
    const float* __restrict__ src,
    const float* __restrict__ b,
    const int* __restrict__ dst_idx,   // int32 (JAX x64-disabled downcasts int64)
    int* __restrict__ out,
    int E, int N)
{
    extern __shared__ __align__(16) char smem[];
    float* bias_s = reinterpret_cast<float*>(smem + OFF_BIAS);

    const int tid  = threadIdx.x;
    const int wid  = tid >> 5;
    const int lane = tid & 31;

    const int m_base = (wid & 1) * 32;    // warp M tile (rows 0..63)
    const int n_base = (wid >> 1) * 32;   // warp N tile (cols 0..127)
    const int nb8    = n_base >> 3;       // first n8 tile index (4 per warp)

    const int tile_base = blockIdx.x * TILE_M;
    const int rem = min(TILE_M, E - tile_base);

    // ---- bias -> smem ----
    if (tid < D) bias_s[tid] = b[tid];

    // ---- convert src tile fp32 -> bf16 hi/lo into padded SMEM ----
    {
        const float4* srcT = reinterpret_cast<const float4*>(src + (size_t)tile_base * D);
        #pragma unroll
        for (int i = tid; i < TILE_M * D / 4; i += 256) {  // 2048 float4, 8 iters
            int row = i >> 5;
            int col4 = i & 31;
            float4 x;
            if (row < rem) x = __ldcs(&srcT[i]);  // streaming: don't evict W frags
            else x = make_float4(0.f, 0.f, 0.f, 0.f);
            uint32_t h01, l01, h23, l23;
            split2(x.x, x.y, h01, l01);
            split2(x.z, x.w, h23, l23);
            size_t soff = (size_t)row * ROW_BYTES + (size_t)col4 * 8;
            *reinterpret_cast<uint2*>(smem + OFF_A_HI + soff) = make_uint2(h01, h23);
            *reinterpret_cast<uint2*>(smem + OFF_A_LO + soff) = make_uint2(l01, l23);
        }
    }

    __syncthreads();

    // ---- ldmatrix base addresses for A ----
    const uint32_t sb = smem_to_u32(smem);
    uint32_t aHi = sb + OFF_A_HI + (uint32_t)(m_base + (lane & 15)) * ROW_BYTES + (uint32_t)(lane >> 4) * 16;
    uint32_t aLo = aHi + (OFF_A_LO - OFF_A_HI);

    float acc[2][4][4];
    #pragma unroll
    for (int mt = 0; mt < 2; mt++)
        #pragma unroll
        for (int nt = 0; nt < 4; nt++)
            #pragma unroll
            for (int c = 0; c < 4; c++) acc[mt][nt][c] = 0.f;

    // ---- mainloop: K=128 in 8 k16 steps; B fragments from global (L1-hot) ----
    #pragma unroll
    for (int k = 0; k < 8; k++) {
        uint32_t ah[2][4], al[2][4];
        #pragma unroll
        for (int mt = 0; mt < 2; mt++) {
            LDSM4(ah[mt], aHi + (uint32_t)mt * 16 * ROW_BYTES + (uint32_t)k * 32);
            LDSM4(al[mt], aLo + (uint32_t)mt * 16 * ROW_BYTES + (uint32_t)k * 32);
        }
        const int fbase = (k * 16 + nb8) * 32 + lane;
        #pragma unroll
        for (int nt = 0; nt < 4; nt++) {
            const uint2 Bh = g_Wf_hi[fbase + nt * 32];
            const uint2 Bl = g_Wf_lo[fbase + nt * 32];
            #pragma unroll
            for (int mt = 0; mt < 2; mt++) {
                MMA_BF16(acc[mt][nt], ah[mt], Bh.x, Bh.y);
                MMA_BF16(acc[mt][nt], al[mt], Bh.x, Bh.y);
                MMA_BF16(acc[mt][nt], ah[mt], Bl.x, Bl.y);
            }
        }
    }

    __syncthreads();  // all warps done reading A smem -> safe to reuse as stage

    // ---- epilogue: bias + relu -> fp32 stage in SMEM ----
    {
        float* stage = reinterpret_cast<float*>(smem);
        const int r0 = m_base + (lane >> 2);
        const int cb = 2 * (lane & 3);
        #pragma unroll
        for (int mt = 0; mt < 2; mt++) {
            #pragma unroll
            for (int nt = 0; nt < 4; nt++) {
                int col = n_base + nt * 8 + cb;
                float bv0 = bias_s[col], bv1 = bias_s[col + 1];
                int rr = r0 + mt * 16;
                stage[rr * STAGE_STRIDE + col]           = fmaxf(acc[mt][nt][0] + bv0, 0.f);
                stage[rr * STAGE_STRIDE + col + 1]       = fmaxf(acc[mt][nt][1] + bv1, 0.f);
                stage[(rr + 8) * STAGE_STRIDE + col]     = fmaxf(acc[mt][nt][2] + bv0, 0.f);
                stage[(rr + 8) * STAGE_STRIDE + col + 1] = fmaxf(acc[mt][nt][3] + bv1, 0.f);
            }
        }
    }
    __syncthreads();

    // ---- coalesced fire-and-forget atomicMax scatter (REDG: no return wait) ----
    {
        const float* stage = reinterpret_cast<const float*>(smem);
        const int c0 = 4 * lane;  // lane owns cols [4*lane, 4*lane+4)
        for (int rr = wid; rr < rem; rr += 8) {  // 8 rows per warp
            int dst = dst_idx[tile_base + rr];
            if ((unsigned)dst >= (unsigned)N) continue;  // safety clamp
            int* op = out + (size_t)dst * D + c0;
            const float* sp = &stage[rr * STAGE_STRIDE + c0];
            // relu => values >= 0; init 0xFF800000 => signed-int max == float max
            atomicMax(op + 0, __float_as_int(sp[0]));
            atomicMax(op + 1, __float_as_int(sp[1]));
            atomicMax(op + 2, __float_as_int(sp[2]));
            atomicMax(op + 3, __float_as_int(sp[3]));
        }
    }
}

// ============================================================================
// Launch
// ============================================================================
extern "C" void kernel_launch(void* const* d_in, const int* in_sizes, int n_in,
                              void* d_out, int out_size) {
    const float* src     = (const float*)d_in[0];
    const float* W       = (const float*)d_in[1];
    const float* b       = (const float*)d_in[2];
    const int*   dst     = (const int*)d_in[3];   // int32 on device

    const int E = in_sizes[0] / D;
    const int N = out_size / D;
    const int tiles = (E + TILE_M - 1) / TILE_M;

    // 0: merged prep (init out to -inf + pack W fragments)
    int n4 = out_size / 4;
    int init_blocks = (n4 + 255) / 256;
    int frag_blocks = (8 * 16 * 32 + 255) / 256;
    prep_kernel<<<init_blocks + frag_blocks, 256>>>((int4*)d_out, n4, W);

    // 1: fused GEMM + scatter-max
    cudaFuncSetAttribute(fused_kernel, cudaFuncAttributeMaxDynamicSharedMemorySize,
                         SMEM_TOTAL);
    fused_kernel<<<tiles, 256, SMEM_TOTAL>>>(src, b, dst, (int*)d_out, E, N);
}

// round 10
// speedup vs baseline: 1.7723x; 1.1887x over previous
#include <cuda_runtime.h>
#include <cuda_fp16.h>
#include <stdint.h>

// ============================================================================
// Problem constants / layout
// ============================================================================
#define D 128
#define TILE_M 128

#define ROW_BYTES  272            // padded fp16 row (136 halves): stride%128=16 -> ldmatrix conflict-free
#define STAGE_STRIDE 132          // fp32 stage row stride

// SMEM layout (bytes):
//   [0, 34816)   A tile (fp16, single table)
//   [0, 67584)   stage buffer (fp32 128x132) -- reuses/extends over A after MMA
//   [67584]      bias (128 floats)
#define OFF_A      0
#define OFF_BIAS   67584
#define SMEM_TOTAL 68096

// ============================================================================
// PTX helpers (base ISA only: ldmatrix / mma.sync)
// ============================================================================
__device__ __forceinline__ uint32_t smem_to_u32(const void* p) {
    uint32_t a;
    asm("{ .reg .u64 t; cvta.to.shared.u64 t, %1; cvt.u32.u64 %0, t; }" : "=r"(a) : "l"(p));
    return a;
}

#define LDSM4(r, addr) \
    asm volatile("ldmatrix.sync.aligned.m8n8.x4.shared.b16 {%0,%1,%2,%3}, [%4];" \
        : "=r"((r)[0]), "=r"((r)[1]), "=r"((r)[2]), "=r"((r)[3]) : "r"(addr))

#define MMA_F16(c, a, b0, b1) \
    asm volatile("mma.sync.aligned.m16n8k16.row.col.f32.f16.f16.f32 " \
        "{%0,%1,%2,%3},{%4,%5,%6,%7},{%8,%9},{%0,%1,%2,%3};" \
        : "+f"((c)[0]), "+f"((c)[1]), "+f"((c)[2]), "+f"((c)[3]) \
        : "r"((a)[0]), "r"((a)[1]), "r"((a)[2]), "r"((a)[3]), \
          "r"(b0), "r"(b1))

// ============================================================================
// W in B-fragment order: [kstep(8)][n8tile(16)][lane(32)] -> uint2 {b0, b1}
// fp16 hi/lo split (hi = rn_f16(w), lo = rn_f16(w - hi); residual ~2^-22)
// ============================================================================
__device__ uint2 g_Wf_hi[8 * 16 * 32];  // 32 KB
__device__ uint2 g_Wf_lo[8 * 16 * 32];  // 32 KB

// fp32 pair -> packed fp16 hi pair + fp16 lo pair
__device__ __forceinline__ void splitf16_2(float x0, float x1, uint32_t& hi, uint32_t& lo) {
    __half h0 = __float2half_rn(x0);
    __half h1 = __float2half_rn(x1);
    __half l0 = __float2half_rn(x0 - __half2float(h0));
    __half l1 = __float2half_rn(x1 - __half2float(h1));
    hi = (uint32_t)__half_as_ushort(h0) | ((uint32_t)__half_as_ushort(h1) << 16);
    lo = (uint32_t)__half_as_ushort(l0) | ((uint32_t)__half_as_ushort(l1) << 16);
}

// fp32 pair -> packed fp16 pair (round-to-nearest)
__device__ __forceinline__ uint32_t packf16(float x0, float x1) {
    __half h0 = __float2half_rn(x0);
    __half h1 = __float2half_rn(x1);
    return (uint32_t)__half_as_ushort(h0) | ((uint32_t)__half_as_ushort(h1) << 16);
}

// ============================================================================
// Kernel 0 (merged prep): init out to -inf AND pack W into fp16 hi/lo fragments.
// ============================================================================
__global__ void prep_kernel(int4* __restrict__ out, int n4, const float* __restrict__ W) {
    const int init_blocks = (n4 + 255) / 256;
    if ((int)blockIdx.x < init_blocks) {
        int i = blockIdx.x * 256 + threadIdx.x;
        if (i < n4) {
            const int m = 0xff800000;  // -inf
            out[i] = make_int4(m, m, m, m);
        }
    } else {
        int i = (blockIdx.x - init_blocks) * 256 + threadIdx.x;  // 0 .. 4095
        if (i < 8 * 16 * 32) {
            int lane = i & 31;
            int n8t  = (i >> 5) & 15;
            int kst  = i >> 9;
            int n  = n8t * 8 + (lane >> 2);
            int k0 = kst * 16 + (lane & 3) * 2;
            const float* Wr = W + (size_t)n * D;
            uint32_t h0, l0, h1, l1;
            splitf16_2(Wr[k0],     Wr[k0 + 1], h0, l0);
            splitf16_2(Wr[k0 + 8], Wr[k0 + 9], h1, l1);
            g_Wf_hi[i] = make_uint2(h0, h1);
            g_Wf_lo[i] = make_uint2(l0, l1);
        }
    }
}

// ============================================================================
// Kernel 1: fused GEMM (mma.sync fp16, 2-pass: A*W_hi + A*W_lo, fp32 accum)
//           + bias + relu + coalesced scatter-max
// ============================================================================
__global__ __launch_bounds__(256, 2) void fused_kernel(
    const float* __restrict__ src,
    const float* __restrict__ b,
    const int* __restrict__ dst_idx,   // int32 (JAX x64-disabled downcasts int64)
    int* __restrict__ out,
    int E, int N)
{
    extern __shared__ __align__(16) char smem[];
    float* bias_s = reinterpret_cast<float*>(smem + OFF_BIAS);

    const int tid  = threadIdx.x;
    const int wid  = tid >> 5;
    const int lane = tid & 31;

    const int m_base = (wid & 3) * 32;   // warp M tile (rows)
    const int n_base = (wid >> 2) * 64;  // warp N tile (cols)
    const int nb8    = n_base >> 3;      // first n8 tile index

    const int tile_base = blockIdx.x * TILE_M;
    const int rem = min(TILE_M, E - tile_base);

    // ---- bias -> smem ----
    if (tid < D) bias_s[tid] = b[tid];

    // ---- convert src tile fp32 -> fp16 (single table) into padded SMEM ----
    {
        const float4* srcT = reinterpret_cast<const float4*>(src + (size_t)tile_base * D);
        #pragma unroll
        for (int i = tid; i < TILE_M * D / 4; i += 256) {  // 4096 float4, 16 iters
            int row = i >> 5;
            int col4 = i & 31;
            float4 x;
            if (row < rem) x = __ldcs(&srcT[i]);  // streaming: don't evict W frags
            else x = make_float4(0.f, 0.f, 0.f, 0.f);
            uint2 h = make_uint2(packf16(x.x, x.y), packf16(x.z, x.w));
            *reinterpret_cast<uint2*>(smem + OFF_A + (size_t)row * ROW_BYTES + (size_t)col4 * 8) = h;
        }
    }

    __syncthreads();

    // ---- ldmatrix base address for A ----
    const uint32_t sb = smem_to_u32(smem);
    uint32_t aBase = sb + OFF_A + (uint32_t)(m_base + (lane & 15)) * ROW_BYTES + (uint32_t)(lane >> 4) * 16;

    float acc[2][8][4];
    #pragma unroll
    for (int mt = 0; mt < 2; mt++)
        #pragma unroll
        for (int nt = 0; nt < 8; nt++)
            #pragma unroll
            for (int c = 0; c < 4; c++) acc[mt][nt][c] = 0.f;

    // ---- mainloop: K=128 in 8 k16 steps; 2 MMA passes (W_hi, W_lo) ----
    #pragma unroll
    for (int k = 0; k < 8; k++) {
        uint32_t a[2][4];
        #pragma unroll
        for (int mt = 0; mt < 2; mt++)
            LDSM4(a[mt], aBase + (uint32_t)mt * 16 * ROW_BYTES + (uint32_t)k * 32);
        const int fbase = (k * 16 + nb8) * 32 + lane;
        #pragma unroll
        for (int nt = 0; nt < 8; nt++) {
            const uint2 Bh = g_Wf_hi[fbase + nt * 32];
            const uint2 Bl = g_Wf_lo[fbase + nt * 32];
            #pragma unroll
            for (int mt = 0; mt < 2; mt++) {
                MMA_F16(acc[mt][nt], a[mt], Bh.x, Bh.y);
                MMA_F16(acc[mt][nt], a[mt], Bl.x, Bl.y);
            }
        }
    }

    __syncthreads();  // all warps done reading A smem -> safe to reuse as stage

    // ---- epilogue: bias + relu -> fp32 stage in SMEM ----
    {
        float* stage = reinterpret_cast<float*>(smem);
        const int r0 = m_base + (lane >> 2);
        const int cb = 2 * (lane & 3);
        #pragma unroll
        for (int mt = 0; mt < 2; mt++) {
            #pragma unroll
            for (int nt = 0; nt < 8; nt++) {
                int col = n_base + nt * 8 + cb;
                float bv0 = bias_s[col], bv1 = bias_s[col + 1];
                int rr = r0 + mt * 16;
                stage[rr * STAGE_STRIDE + col]           = fmaxf(acc[mt][nt][0] + bv0, 0.f);
                stage[rr * STAGE_STRIDE + col + 1]       = fmaxf(acc[mt][nt][1] + bv1, 0.f);
                stage[(rr + 8) * STAGE_STRIDE + col]     = fmaxf(acc[mt][nt][2] + bv0, 0.f);
                stage[(rr + 8) * STAGE_STRIDE + col + 1] = fmaxf(acc[mt][nt][3] + bv1, 0.f);
            }
        }
    }
    __syncthreads();

    // ---- coalesced fire-and-forget atomicMax scatter (REDG: no return wait) ----
    {
        const float* stage = reinterpret_cast<const float*>(smem);
        for (int rr = wid; rr < rem; rr += 8) {
            int dst = dst_idx[tile_base + rr];
            if ((unsigned)dst >= (unsigned)N) continue;  // safety clamp
            int* op = out + (size_t)dst * D;
            #pragma unroll
            for (int kk = 0; kk < 4; kk++) {
                int col = lane + kk * 32;  // 128B per atomic instruction: fully coalesced
                // relu => values >= 0; init 0xFF800000 => signed-int max == float max
                atomicMax(op + col, __float_as_int(stage[rr * STAGE_STRIDE + col]));
            }
        }
    }
}

// ============================================================================
// Launch
// ============================================================================
extern "C" void kernel_launch(void* const* d_in, const int* in_sizes, int n_in,
                              void* d_out, int out_size) {
    const float* src     = (const float*)d_in[0];
    const float* W       = (const float*)d_in[1];
    const float* b       = (const float*)d_in[2];
    const int*   dst     = (const int*)d_in[3];   // int32 on device

    const int E = in_sizes[0] / D;
    const int N = out_size / D;
    const int tiles = (E + TILE_M - 1) / TILE_M;

    // 0: merged prep (init out to -inf + pack W fp16 hi/lo fragments)
    int n4 = out_size / 4;
    int init_blocks = (n4 + 255) / 256;
    int frag_blocks = (8 * 16 * 32 + 255) / 256;
    prep_kernel<<<init_blocks + frag_blocks, 256>>>((int4*)d_out, n4, W);

    // 1: fused GEMM + scatter-max
    cudaFuncSetAttribute(fused_kernel, cudaFuncAttributeMaxDynamicSharedMemorySize,
                         SMEM_TOTAL);
    fused_kernel<<<tiles, 256, SMEM_TOTAL>>>(src, b, dst, (int*)d_out, E, N);
}

// round 11
// speedup vs baseline: 1.7726x; 1.0001x over previous
#include <cuda_runtime.h>
#include <cuda_fp16.h>
#include <stdint.h>

// ============================================================================
// Problem constants / layout
// ============================================================================
#define D 128
#define TILE_M 128

#define ROW_BYTES  272            // padded fp16 row (136 halves): stride%128=16 -> ldmatrix conflict-free
#define STAGE_STRIDE 132          // fp32 stage row stride

// SMEM layout (bytes):
//   [0, 34816)   A tile (fp16, single table)
//   [0, 67584)   stage buffer (fp32 128x132) -- reuses/extends over A after MMA
//   [67584]      bias (128 floats)
#define OFF_A      0
#define OFF_BIAS   67584
#define SMEM_TOTAL 68096

// ============================================================================
// PTX helpers (base ISA only: ldmatrix / mma.sync)
// ============================================================================
__device__ __forceinline__ uint32_t smem_to_u32(const void* p) {
    uint32_t a;
    asm("{ .reg .u64 t; cvta.to.shared.u64 t, %1; cvt.u32.u64 %0, t; }" : "=r"(a) : "l"(p));
    return a;
}

#define LDSM4(r, addr) \
    asm volatile("ldmatrix.sync.aligned.m8n8.x4.shared.b16 {%0,%1,%2,%3}, [%4];" \
        : "=r"((r)[0]), "=r"((r)[1]), "=r"((r)[2]), "=r"((r)[3]) : "r"(addr))

#define MMA_F16(c, a, b0, b1) \
    asm volatile("mma.sync.aligned.m16n8k16.row.col.f32.f16.f16.f32 " \
        "{%0,%1,%2,%3},{%4,%5,%6,%7},{%8,%9},{%0,%1,%2,%3};" \
        : "+f"((c)[0]), "+f"((c)[1]), "+f"((c)[2]), "+f"((c)[3]) \
        : "r"((a)[0]), "r"((a)[1]), "r"((a)[2]), "r"((a)[3]), \
          "r"(b0), "r"(b1))

// ============================================================================
// W in B-fragment order: [kstep(8)][n8tile(16)][lane(32)] -> uint2 {b0, b1}
// fp16 hi/lo split (hi = rn_f16(w), lo = rn_f16(w - hi); residual ~2^-22)
// ============================================================================
__device__ uint2 g_Wf_hi[8 * 16 * 32];  // 32 KB
__device__ uint2 g_Wf_lo[8 * 16 * 32];  // 32 KB

// fp32 pair -> packed fp16 hi pair + fp16 lo pair
__device__ __forceinline__ void splitf16_2(float x0, float x1, uint32_t& hi, uint32_t& lo) {
    __half h0 = __float2half_rn(x0);
    __half h1 = __float2half_rn(x1);
    __half l0 = __float2half_rn(x0 - __half2float(h0));
    __half l1 = __float2half_rn(x1 - __half2float(h1));
    hi = (uint32_t)__half_as_ushort(h0) | ((uint32_t)__half_as_ushort(h1) << 16);
    lo = (uint32_t)__half_as_ushort(l0) | ((uint32_t)__half_as_ushort(l1) << 16);
}

// fp32 pair -> packed fp16 pair (round-to-nearest)
__device__ __forceinline__ uint32_t packf16(float x0, float x1) {
    __half h0 = __float2half_rn(x0);
    __half h1 = __float2half_rn(x1);
    return (uint32_t)__half_as_ushort(h0) | ((uint32_t)__half_as_ushort(h1) << 16);
}

// ============================================================================
// Kernel 0 (merged prep): init out to -inf AND pack W into fp16 hi/lo fragments.
// ============================================================================
__global__ void prep_kernel(int4* __restrict__ out, int n4, const float* __restrict__ W) {
    const int init_blocks = (n4 + 255) / 256;
    if ((int)blockIdx.x < init_blocks) {
        int i = blockIdx.x * 256 + threadIdx.x;
        if (i < n4) {
            const int m = 0xff800000;  // -inf
            out[i] = make_int4(m, m, m, m);
        }
    } else {
        int i = (blockIdx.x - init_blocks) * 256 + threadIdx.x;  // 0 .. 4095
        if (i < 8 * 16 * 32) {
            int lane = i & 31;
            int n8t  = (i >> 5) & 15;
            int kst  = i >> 9;
            int n  = n8t * 8 + (lane >> 2);
            int k0 = kst * 16 + (lane & 3) * 2;
            const float* Wr = W + (size_t)n * D;
            uint32_t h0, l0, h1, l1;
            splitf16_2(Wr[k0],     Wr[k0 + 1], h0, l0);
            splitf16_2(Wr[k0 + 8], Wr[k0 + 9], h1, l1);
            g_Wf_hi[i] = make_uint2(h0, h1);
            g_Wf_lo[i] = make_uint2(l0, l1);
        }
    }
}

// ============================================================================
// Kernel 1: fused GEMM (mma.sync fp16, 2-pass: A*W_hi + A*W_lo, fp32 accum)
//           + bias + relu + coalesced scatter-max
// ============================================================================
__global__ __launch_bounds__(256, 2) void fused_kernel(
    const float* __restrict__ src,
    const float* __restrict__ b,
    const int* __restrict__ dst_idx,   // int32 (JAX x64-disabled downcasts int64)
    int* __restrict__ out,
    int E, int N)
{
    extern __shared__ __align__(16) char smem[];
    float* bias_s = reinterpret_cast<float*>(smem + OFF_BIAS);

    const int tid  = threadIdx.x;
    const int wid  = tid >> 5;
    const int lane = tid & 31;

    const int m_base = (wid & 3) * 32;   // warp M tile (rows)
    const int n_base = (wid >> 2) * 64;  // warp N tile (cols)
    const int nb8    = n_base >> 3;      // first n8 tile index

    const int tile_base = blockIdx.x * TILE_M;
    const int rem = min(TILE_M, E - tile_base);

    // ---- bias -> smem ----
    if (tid < D) bias_s[tid] = b[tid];

    // ---- convert src tile fp32 -> fp16 into padded SMEM.
    //      BATCHED loads (MLP=8): issue 8 independent LDG.128, then convert.
    //      (R10 did load->convert->store per iter: MLP~2, DRAM latency-bound.)
    {
        const float4* srcT = reinterpret_cast<const float4*>(src + (size_t)tile_base * D);
        const float4 z4 = make_float4(0.f, 0.f, 0.f, 0.f);
        #pragma unroll
        for (int half = 0; half < 2; half++) {
            float4 xa[8];
            // phase A: 8 independent loads in flight
            #pragma unroll
            for (int u = 0; u < 8; u++) {
                int i = tid + (half * 8 + u) * 256;
                int row = i >> 5;
                xa[u] = (row < rem) ? __ldcs(&srcT[i]) : z4;
            }
            // phase B: convert + store
            #pragma unroll
            for (int u = 0; u < 8; u++) {
                int i = tid + (half * 8 + u) * 256;
                int row = i >> 5;
                int col4 = i & 31;
                uint2 h = make_uint2(packf16(xa[u].x, xa[u].y), packf16(xa[u].z, xa[u].w));
                *reinterpret_cast<uint2*>(smem + OFF_A + (size_t)row * ROW_BYTES + (size_t)col4 * 8) = h;
            }
        }
    }

    __syncthreads();

    // ---- ldmatrix base address for A ----
    const uint32_t sb = smem_to_u32(smem);
    uint32_t aBase = sb + OFF_A + (uint32_t)(m_base + (lane & 15)) * ROW_BYTES + (uint32_t)(lane >> 4) * 16;

    float acc[2][8][4];
    #pragma unroll
    for (int mt = 0; mt < 2; mt++)
        #pragma unroll
        for (int nt = 0; nt < 8; nt++)
            #pragma unroll
            for (int c = 0; c < 4; c++) acc[mt][nt][c] = 0.f;

    // ---- mainloop: K=128 in 8 k16 steps; 2 MMA passes (W_hi, W_lo) ----
    #pragma unroll
    for (int k = 0; k < 8; k++) {
        uint32_t a[2][4];
        #pragma unroll
        for (int mt = 0; mt < 2; mt++)
            LDSM4(a[mt], aBase + (uint32_t)mt * 16 * ROW_BYTES + (uint32_t)k * 32);
        const int fbase = (k * 16 + nb8) * 32 + lane;
        #pragma unroll
        for (int nt = 0; nt < 8; nt++) {
            const uint2 Bh = g_Wf_hi[fbase + nt * 32];
            const uint2 Bl = g_Wf_lo[fbase + nt * 32];
            #pragma unroll
            for (int mt = 0; mt < 2; mt++) {
                MMA_F16(acc[mt][nt], a[mt], Bh.x, Bh.y);
                MMA_F16(acc[mt][nt], a[mt], Bl.x, Bl.y);
            }
        }
    }

    __syncthreads();  // all warps done reading A smem -> safe to reuse as stage

    // ---- epilogue: bias + relu -> fp32 stage in SMEM ----
    {
        float* stage = reinterpret_cast<float*>(smem);
        const int r0 = m_base + (lane >> 2);
        const int cb = 2 * (lane & 3);
        #pragma unroll
        for (int mt = 0; mt < 2; mt++) {
            #pragma unroll
            for (int nt = 0; nt < 8; nt++) {
                int col = n_base + nt * 8 + cb;
                float bv0 = bias_s[col], bv1 = bias_s[col + 1];
                int rr = r0 + mt * 16;
                stage[rr * STAGE_STRIDE + col]           = fmaxf(acc[mt][nt][0] + bv0, 0.f);
                stage[rr * STAGE_STRIDE + col + 1]       = fmaxf(acc[mt][nt][1] + bv1, 0.f);
                stage[(rr + 8) * STAGE_STRIDE + col]     = fmaxf(acc[mt][nt][2] + bv0, 0.f);
                stage[(rr + 8) * STAGE_STRIDE + col + 1] = fmaxf(acc[mt][nt][3] + bv1, 0.f);
            }
        }
    }
    __syncthreads();

    // ---- coalesced fire-and-forget atomicMax scatter (REDG: no return wait) ----
    {
        const float* stage = reinterpret_cast<const float*>(smem);
        for (int rr = wid; rr < rem; rr += 8) {
            int dst = dst_idx[tile_base + rr];
            if ((unsigned)dst >= (unsigned)N) continue;  // safety clamp
            int* op = out + (size_t)dst * D;
            #pragma unroll
            for (int kk = 0; kk < 4; kk++) {
                int col = lane + kk * 32;  // 128B per atomic instruction: fully coalesced
                // relu => values >= 0; init 0xFF800000 => signed-int max == float max
                atomicMax(op + col, __float_as_int(stage[rr * STAGE_STRIDE + col]));
            }
        }
    }
}

// ============================================================================
// Launch
// ============================================================================
extern "C" void kernel_launch(void* const* d_in, const int* in_sizes, int n_in,
                              void* d_out, int out_size) {
    const float* src     = (const float*)d_in[0];
    const float* W       = (const float*)d_in[1];
    const float* b       = (const float*)d_in[2];
    const int*   dst     = (const int*)d_in[3];   // int32 on device

    const int E = in_sizes[0] / D;
    const int N = out_size / D;
    const int tiles = (E + TILE_M - 1) / TILE_M;

    // 0: merged prep (init out to -inf + pack W fp16 hi/lo fragments)
    int n4 = out_size / 4;
    int init_blocks = (n4 + 255) / 256;
    int frag_blocks = (8 * 16 * 32 + 255) / 256;
    prep_kernel<<<init_blocks + frag_blocks, 256>>>((int4*)d_out, n4, W);

    // 1: fused GEMM + scatter-max
    cudaFuncSetAttribute(fused_kernel, cudaFuncAttributeMaxDynamicSharedMemorySize,
                         SMEM_TOTAL);
    fused_kernel<<<tiles, 256, SMEM_TOTAL>>>(src, b, dst, (int*)d_out, E, N);
}

// round 13
// speedup vs baseline: 1.8745x; 1.0575x over previous
#include <cuda_runtime.h>
#include <cuda_fp16.h>
#include <stdint.h>

// ============================================================================
// Problem constants / layout
// ============================================================================
#define D 128
#define TILE_M 64                 // persistent tile: 64 edges x 128 cols

#define ROW_BYTES  272            // padded fp16 row (136 halves): stride%128=16 -> ldmatrix conflict-free

// SMEM layout (bytes): tiny -> L1D carveout keeps the 64KB W-frag table resident.
#define OFF_A      0              // 64 x 272B = 17408 (fp16 A tile)
#define OFF_BIAS   17408          // 128 floats
#define OFF_DST    17920          // 64 ints
#define SMEM_TOTAL 18176

// ============================================================================
// PTX helpers (base ISA only: ldmatrix / mma.sync)
// ============================================================================
__device__ __forceinline__ uint32_t smem_to_u32(const void* p) {
    uint32_t a;
    asm("{ .reg .u64 t; cvta.to.shared.u64 t, %1; cvt.u32.u64 %0, t; }" : "=r"(a) : "l"(p));
    return a;
}

#define LDSM4(r, addr) \
    asm volatile("ldmatrix.sync.aligned.m8n8.x4.shared.b16 {%0,%1,%2,%3}, [%4];" \
        : "=r"((r)[0]), "=r"((r)[1]), "=r"((r)[2]), "=r"((r)[3]) : "r"(addr))

#define MMA_F16(c, a, b0, b1) \
    asm volatile("mma.sync.aligned.m16n8k16.row.col.f32.f16.f16.f32 " \
        "{%0,%1,%2,%3},{%4,%5,%6,%7},{%8,%9},{%0,%1,%2,%3};" \
        : "+f"((c)[0]), "+f"((c)[1]), "+f"((c)[2]), "+f"((c)[3]) \
        : "r"((a)[0]), "r"((a)[1]), "r"((a)[2]), "r"((a)[3]), \
          "r"(b0), "r"(b1))

// ============================================================================
// W in B-fragment order: [kstep(8)][n8tile(16)][lane(32)] -> uint2 {b0, b1}
// fp16 hi/lo split (hi = rn_f16(w), lo = rn_f16(w - hi))
// ============================================================================
__device__ uint2 g_Wf_hi[8 * 16 * 32];  // 32 KB
__device__ uint2 g_Wf_lo[8 * 16 * 32];  // 32 KB

__device__ __forceinline__ void splitf16_2(float x0, float x1, uint32_t& hi, uint32_t& lo) {
    __half h0 = __float2half_rn(x0);
    __half h1 = __float2half_rn(x1);
    __half l0 = __float2half_rn(x0 - __half2float(h0));
    __half l1 = __float2half_rn(x1 - __half2float(h1));
    hi = (uint32_t)__half_as_ushort(h0) | ((uint32_t)__half_as_ushort(h1) << 16);
    lo = (uint32_t)__half_as_ushort(l0) | ((uint32_t)__half_as_ushort(l1) << 16);
}

__device__ __forceinline__ uint32_t packf16(float x0, float x1) {
    __half h0 = __float2half_rn(x0);
    __half h1 = __float2half_rn(x1);
    return (uint32_t)__half_as_ushort(h0) | ((uint32_t)__half_as_ushort(h1) << 16);
}

// ============================================================================
// Kernel 0 (merged prep): init out to -inf AND pack W into fp16 hi/lo fragments.
// ============================================================================
__global__ void prep_kernel(int4* __restrict__ out, int n4, const float* __restrict__ W) {
    const int init_blocks = (n4 + 255) / 256;
    if ((int)blockIdx.x < init_blocks) {
        int i = blockIdx.x * 256 + threadIdx.x;
        if (i < n4) {
            const int m = 0xff800000;  // -inf
            out[i] = make_int4(m, m, m, m);
        }
    } else {
        int i = (blockIdx.x - init_blocks) * 256 + threadIdx.x;  // 0 .. 4095
        if (i < 8 * 16 * 32) {
            int lane = i & 31;
            int n8t  = (i >> 5) & 15;
            int kst  = i >> 9;
            int n  = n8t * 8 + (lane >> 2);
            int k0 = kst * 16 + (lane & 3) * 2;
            const float* Wr = W + (size_t)n * D;
            uint32_t h0, l0, h1, l1;
            splitf16_2(Wr[k0],     Wr[k0 + 1], h0, l0);
            splitf16_2(Wr[k0 + 8], Wr[k0 + 9], h1, l1);
            g_Wf_hi[i] = make_uint2(h0, h1);
            g_Wf_lo[i] = make_uint2(l0, l1);
        }
    }
}

// ============================================================================
// Kernel 1: PERSISTENT fused GEMM + scatter-max, TILE_M=64.
// pend[8] per thread = 2048 float4 = EXACTLY one 64x128 tile (R12 bug: it
// covered only half a 128-row tile). Next tile's loads are issued before the
// MMA so DRAM latency hides under tensor work. Scatter goes directly from
// MMA fragments (no stage buffer).
// ============================================================================
__global__ __launch_bounds__(256, 2) void fused_kernel(
    const float* __restrict__ src,
    const float* __restrict__ b,
    const int* __restrict__ dst_idx,   // int32 (JAX x64-disabled downcasts int64)
    int* __restrict__ out,
    int E, int N, int tiles)
{
    extern __shared__ __align__(16) char smem[];
    float* bias_s = reinterpret_cast<float*>(smem + OFF_BIAS);
    int*   dst_s  = reinterpret_cast<int*>(smem + OFF_DST);

    const int tid  = threadIdx.x;
    const int wid  = tid >> 5;
    const int lane = tid & 31;

    const int m_base = (wid & 1) * 32;    // warp M tile (rows 0..63)
    const int n_base = (wid >> 1) * 32;   // warp N tile (cols 0..127)
    const int nb8    = n_base >> 3;       // first n8 tile index
    const int cb     = 2 * (lane & 3);

    if (tid < D) bias_s[tid] = b[tid];

    const uint32_t sb = smem_to_u32(smem);
    const uint32_t aBase = sb + OFF_A
        + (uint32_t)(m_base + (lane & 15)) * ROW_BYTES + (uint32_t)(lane >> 4) * 16;

    const float4* srcT = reinterpret_cast<const float4*>(src);
    const float4 z4 = make_float4(0.f, 0.f, 0.f, 0.f);

    // ---- initial prefetch: tile blockIdx.x (64 rows = 2048 float4) ----
    float4 pend[8];
    {
        int tb = blockIdx.x * TILE_M;
        int rm = min(TILE_M, E - tb);
        #pragma unroll
        for (int u = 0; u < 8; u++) {
            int i = tid + u * 256;           // 0..2047 -> row = i>>5 in 0..63
            pend[u] = ((i >> 5) < rm) ? __ldcs(&srcT[(size_t)tb * 32 + i]) : z4;
        }
    }

    for (int t = blockIdx.x; t < tiles; t += gridDim.x) {
        const int tile_base = t * TILE_M;
        const int rem = min(TILE_M, E - tile_base);

        __syncthreads();  // previous tile fully consumed (A + dst_s free)

        // ---- drain pending regs -> fp16 A tile in SMEM; load dst slice ----
        #pragma unroll
        for (int u = 0; u < 8; u++) {
            int i = tid + u * 256;
            int row = i >> 5;
            int col4 = i & 31;
            uint2 h = make_uint2(packf16(pend[u].x, pend[u].y),
                                 packf16(pend[u].z, pend[u].w));
            *reinterpret_cast<uint2*>(smem + OFF_A + (size_t)row * ROW_BYTES + (size_t)col4 * 8) = h;
        }
        if (tid < TILE_M) dst_s[tid] = (tid < rem) ? dst_idx[tile_base + tid] : -1;

        __syncthreads();  // A tile + dst_s ready

        // ---- issue next tile's loads NOW (complete during MMA below) ----
        {
            int tn = t + gridDim.x;
            if (tn < tiles) {
                int tbn = tn * TILE_M;
                int rmn = min(TILE_M, E - tbn);
                #pragma unroll
                for (int u = 0; u < 8; u++) {
                    int i = tid + u * 256;
                    pend[u] = ((i >> 5) < rmn) ? __ldcs(&srcT[(size_t)tbn * 32 + i]) : z4;
                }
            }
        }

        // ---- MMA: K=128 in 8 k16 steps; 2 passes (W_hi, W_lo), fp32 accum ----
        float acc[2][4][4];
        #pragma unroll
        for (int mt = 0; mt < 2; mt++)
            #pragma unroll
            for (int nt = 0; nt < 4; nt++)
                #pragma unroll
                for (int c = 0; c < 4; c++) acc[mt][nt][c] = 0.f;

        #pragma unroll
        for (int k = 0; k < 8; k++) {
            uint32_t a[2][4];
            #pragma unroll
            for (int mt = 0; mt < 2; mt++)
                LDSM4(a[mt], aBase + (uint32_t)mt * 16 * ROW_BYTES + (uint32_t)k * 32);
            const int fbase = (k * 16 + nb8) * 32 + lane;
            #pragma unroll
            for (int nt = 0; nt < 4; nt++) {
                const uint2 Bh = g_Wf_hi[fbase + nt * 32];
                const uint2 Bl = g_Wf_lo[fbase + nt * 32];
                #pragma unroll
                for (int mt = 0; mt < 2; mt++) {
                    MMA_F16(acc[mt][nt], a[mt], Bh.x, Bh.y);
                    MMA_F16(acc[mt][nt], a[mt], Bl.x, Bl.y);
                }
            }
        }

        // ---- scatter DIRECTLY from fragments: bias + relu + atomicMax ----
        // thread holds rows rb+mt*16+h*8, cols n_base+nt*8+cb (+1)
        {
            const int rb = m_base + (lane >> 2);
            #pragma unroll
            for (int mt = 0; mt < 2; mt++) {
                #pragma unroll
                for (int h = 0; h < 2; h++) {
                    int rr = rb + mt * 16 + h * 8;
                    int dst = dst_s[rr];
                    if ((unsigned)dst >= (unsigned)N) continue;  // pad rows: dst=-1
                    int* op = out + (size_t)dst * D;
                    #pragma unroll
                    for (int nt = 0; nt < 4; nt++) {
                        int col = n_base + nt * 8 + cb;
                        float v0 = fmaxf(acc[mt][nt][h * 2 + 0] + bias_s[col], 0.f);
                        float v1 = fmaxf(acc[mt][nt][h * 2 + 1] + bias_s[col + 1], 0.f);
                        // relu => v >= 0; init 0xFF800000 => signed-int max == float max
                        atomicMax(op + col,     __float_as_int(v0));
                        atomicMax(op + col + 1, __float_as_int(v1));
                    }
                }
            }
        }
    }
}

// ============================================================================
// Launch
// ============================================================================
extern "C" void kernel_launch(void* const* d_in, const int* in_sizes, int n_in,
                              void* d_out, int out_size) {
    const float* src     = (const float*)d_in[0];
    const float* W       = (const float*)d_in[1];
    const float* b       = (const float*)d_in[2];
    const int*   dst     = (const int*)d_in[3];   // int32 on device

    const int E = in_sizes[0] / D;
    const int N = out_size / D;
    const int tiles = (E + TILE_M - 1) / TILE_M;

    // 0: merged prep (init out to -inf + pack W fp16 hi/lo fragments)
    int n4 = out_size / 4;
    int init_blocks = (n4 + 255) / 256;
    int frag_blocks = (8 * 16 * 32 + 255) / 256;
    prep_kernel<<<init_blocks + frag_blocks, 256>>>((int4*)d_out, n4, W);

    // 1: persistent fused GEMM + scatter-max (2 CTAs/SM x 148 SMs)
    int grid = 296;
    if (grid > tiles) grid = tiles;
    cudaFuncSetAttribute(fused_kernel, cudaFuncAttributeMaxDynamicSharedMemorySize,
                         SMEM_TOTAL);
    fused_kernel<<<grid, 256, SMEM_TOTAL>>>(src, b, dst, (int*)d_out, E, N, tiles);
}

// round 14
// speedup vs baseline: 2.2176x; 1.1831x over previous
#include <cuda_runtime.h>
#include <cuda_fp16.h>
#include <stdint.h>

// ============================================================================
// Problem constants / layout
// ============================================================================
#define D 128
#define TILE_M 64                 // persistent tile: 64 edges x 128 cols

#define ROW_BYTES  272            // padded fp16 row (136 halves): stride%128=16 -> ldmatrix conflict-free

// SMEM layout (bytes): tiny -> L1D carveout keeps the 32KB W-frag table resident.
#define OFF_A      0              // 64 x 272B = 17408 (fp16 A tile)
#define OFF_BIAS   17408          // 128 floats
#define OFF_DST    17920          // 64 ints
#define SMEM_TOTAL 18176

// ============================================================================
// PTX helpers (base ISA only: ldmatrix / mma.sync)
// ============================================================================
__device__ __forceinline__ uint32_t smem_to_u32(const void* p) {
    uint32_t a;
    asm("{ .reg .u64 t; cvta.to.shared.u64 t, %1; cvt.u32.u64 %0, t; }" : "=r"(a) : "l"(p));
    return a;
}

#define LDSM4(r, addr) \
    asm volatile("ldmatrix.sync.aligned.m8n8.x4.shared.b16 {%0,%1,%2,%3}, [%4];" \
        : "=r"((r)[0]), "=r"((r)[1]), "=r"((r)[2]), "=r"((r)[3]) : "r"(addr))

#define MMA_F16(c, a, b0, b1) \
    asm volatile("mma.sync.aligned.m16n8k16.row.col.f32.f16.f16.f32 " \
        "{%0,%1,%2,%3},{%4,%5,%6,%7},{%8,%9},{%0,%1,%2,%3};" \
        : "+f"((c)[0]), "+f"((c)[1]), "+f"((c)[2]), "+f"((c)[3]) \
        : "r"((a)[0]), "r"((a)[1]), "r"((a)[2]), "r"((a)[3]), \
          "r"(b0), "r"(b1))

// ============================================================================
// W in B-fragment order: [kstep(8)][n8tile(16)][lane(32)] -> uint2 {b0, b1}
// SINGLE fp16 table (rel_err budget: A-quant 1.16e-4 measured; W-quant adds
// ~sqrt(2)x -> ~1.7e-4, still 6x under the 1e-3 threshold).
// ============================================================================
__device__ uint2 g_Wf[8 * 16 * 32];  // 32 KB

__device__ __forceinline__ uint32_t packf16(float x0, float x1) {
    __half h0 = __float2half_rn(x0);
    __half h1 = __float2half_rn(x1);
    return (uint32_t)__half_as_ushort(h0) | ((uint32_t)__half_as_ushort(h1) << 16);
}

// ============================================================================
// Kernel 0 (merged prep): init out to -inf AND pack W into fp16 fragments.
// ============================================================================
__global__ void prep_kernel(int4* __restrict__ out, int n4, const float* __restrict__ W) {
    const int init_blocks = (n4 + 255) / 256;
    if ((int)blockIdx.x < init_blocks) {
        int i = blockIdx.x * 256 + threadIdx.x;
        if (i < n4) {
            const int m = 0xff800000;  // -inf
            out[i] = make_int4(m, m, m, m);
        }
    } else {
        int i = (blockIdx.x - init_blocks) * 256 + threadIdx.x;  // 0 .. 4095
        if (i < 8 * 16 * 32) {
            int lane = i & 31;
            int n8t  = (i >> 5) & 15;
            int kst  = i >> 9;
            int n  = n8t * 8 + (lane >> 2);
            int k0 = kst * 16 + (lane & 3) * 2;
            const float* Wr = W + (size_t)n * D;
            g_Wf[i] = make_uint2(packf16(Wr[k0],     Wr[k0 + 1]),
                                 packf16(Wr[k0 + 8], Wr[k0 + 9]));
        }
    }
}

// ============================================================================
// Kernel 1: PERSISTENT fused GEMM + scatter-max, TILE_M=64, single MMA pass.
// Next tile's src loads are register-carried and issued before the MMA so
// DRAM latency hides under tensor work. Scatter directly from fragments.
// ============================================================================
__global__ __launch_bounds__(256, 2) void fused_kernel(
    const float* __restrict__ src,
    const float* __restrict__ b,
    const int* __restrict__ dst_idx,   // int32 (JAX x64-disabled downcasts int64)
    int* __restrict__ out,
    int E, int N, int tiles)
{
    extern __shared__ __align__(16) char smem[];
    float* bias_s = reinterpret_cast<float*>(smem + OFF_BIAS);
    int*   dst_s  = reinterpret_cast<int*>(smem + OFF_DST);

    const int tid  = threadIdx.x;
    const int wid  = tid >> 5;
    const int lane = tid & 31;

    const int m_base = (wid & 1) * 32;    // warp M tile (rows 0..63)
    const int n_base = (wid >> 1) * 32;   // warp N tile (cols 0..127)
    const int nb8    = n_base >> 3;       // first n8 tile index
    const int cb     = 2 * (lane & 3);

    if (tid < D) bias_s[tid] = b[tid];

    const uint32_t sb = smem_to_u32(smem);
    const uint32_t aBase = sb + OFF_A
        + (uint32_t)(m_base + (lane & 15)) * ROW_BYTES + (uint32_t)(lane >> 4) * 16;

    const float4* srcT = reinterpret_cast<const float4*>(src);
    const float4 z4 = make_float4(0.f, 0.f, 0.f, 0.f);

    // ---- initial prefetch: tile blockIdx.x (64 rows = 2048 float4) ----
    float4 pend[8];
    {
        int tb = blockIdx.x * TILE_M;
        int rm = min(TILE_M, E - tb);
        #pragma unroll
        for (int u = 0; u < 8; u++) {
            int i = tid + u * 256;           // 0..2047 -> row = i>>5 in 0..63
            pend[u] = ((i >> 5) < rm) ? __ldcs(&srcT[(size_t)tb * 32 + i]) : z4;
        }
    }

    for (int t = blockIdx.x; t < tiles; t += gridDim.x) {
        const int tile_base = t * TILE_M;
        const int rem = min(TILE_M, E - tile_base);

        __syncthreads();  // previous tile fully consumed (A + dst_s free)

        // ---- drain pending regs -> fp16 A tile in SMEM; load dst slice ----
        #pragma unroll
        for (int u = 0; u < 8; u++) {
            int i = tid + u * 256;
            int row = i >> 5;
            int col4 = i & 31;
            uint2 h = make_uint2(packf16(pend[u].x, pend[u].y),
                                 packf16(pend[u].z, pend[u].w));
            *reinterpret_cast<uint2*>(smem + OFF_A + (size_t)row * ROW_BYTES + (size_t)col4 * 8) = h;
        }
        if (tid < TILE_M) dst_s[tid] = (tid < rem) ? dst_idx[tile_base + tid] : -1;

        __syncthreads();  // A tile + dst_s ready

        // ---- issue next tile's loads NOW (complete during MMA below) ----
        {
            int tn = t + gridDim.x;
            if (tn < tiles) {
                int tbn = tn * TILE_M;
                int rmn = min(TILE_M, E - tbn);
                #pragma unroll
                for (int u = 0; u < 8; u++) {
                    int i = tid + u * 256;
                    pend[u] = ((i >> 5) < rmn) ? __ldcs(&srcT[(size_t)tbn * 32 + i]) : z4;
                }
            }
        }

        // ---- MMA: K=128 in 8 k16 steps; SINGLE pass (fp16 W), fp32 accum ----
        float acc[2][4][4];
        #pragma unroll
        for (int mt = 0; mt < 2; mt++)
            #pragma unroll
            for (int nt = 0; nt < 4; nt++)
                #pragma unroll
                for (int c = 0; c < 4; c++) acc[mt][nt][c] = 0.f;

        #pragma unroll
        for (int k = 0; k < 8; k++) {
            uint32_t a[2][4];
            #pragma unroll
            for (int mt = 0; mt < 2; mt++)
                LDSM4(a[mt], aBase + (uint32_t)mt * 16 * ROW_BYTES + (uint32_t)k * 32);
            const int fbase = (k * 16 + nb8) * 32 + lane;
            #pragma unroll
            for (int nt = 0; nt < 4; nt++) {
                const uint2 B = g_Wf[fbase + nt * 32];
                #pragma unroll
                for (int mt = 0; mt < 2; mt++)
                    MMA_F16(acc[mt][nt], a[mt], B.x, B.y);
            }
        }

        // ---- scatter DIRECTLY from fragments: bias + relu + atomicMax ----
        {
            const int rb = m_base + (lane >> 2);
            #pragma unroll
            for (int mt = 0; mt < 2; mt++) {
                #pragma unroll
                for (int h = 0; h < 2; h++) {
                    int rr = rb + mt * 16 + h * 8;
                    int dst = dst_s[rr];
                    if ((unsigned)dst >= (unsigned)N) continue;  // pad rows: dst=-1
                    int* op = out + (size_t)dst * D;
                    #pragma unroll
                    for (int nt = 0; nt < 4; nt++) {
                        int col = n_base + nt * 8 + cb;
                        float v0 = fmaxf(acc[mt][nt][h * 2 + 0] + bias_s[col], 0.f);
                        float v1 = fmaxf(acc[mt][nt][h * 2 + 1] + bias_s[col + 1], 0.f);
                        // relu => v >= 0; init 0xFF800000 => signed-int max == float max
                        atomicMax(op + col,     __float_as_int(v0));
                        atomicMax(op + col + 1, __float_as_int(v1));
                    }
                }
            }
        }
    }
}

// ============================================================================
// Launch
// ============================================================================
extern "C" void kernel_launch(void* const* d_in, const int* in_sizes, int n_in,
                              void* d_out, int out_size) {
    const float* src     = (const float*)d_in[0];
    const float* W       = (const float*)d_in[1];
    const float* b       = (const float*)d_in[2];
    const int*   dst     = (const int*)d_in[3];   // int32 on device

    const int E = in_sizes[0] / D;
    const int N = out_size / D;
    const int tiles = (E + TILE_M - 1) / TILE_M;

    // 0: merged prep (init out to -inf + pack W fp16 fragments)
    int n4 = out_size / 4;
    int init_blocks = (n4 + 255) / 256;
    int frag_blocks = (8 * 16 * 32 + 255) / 256;
    prep_kernel<<<init_blocks + frag_blocks, 256>>>((int4*)d_out, n4, W);

    // 1: persistent fused GEMM + scatter-max (2 CTAs/SM x 148 SMs)
    int grid = 296;
    if (grid > tiles) grid = tiles;
    cudaFuncSetAttribute(fused_kernel, cudaFuncAttributeMaxDynamicSharedMemorySize,
                         SMEM_TOTAL);
    fused_kernel<<<grid, 256, SMEM_TOTAL>>>(src, b, dst, (int*)d_out, E, N, tiles);
}

// round 15
// speedup vs baseline: 2.6011x; 1.1729x over previous
#include <cuda_runtime.h>
#include <cuda_fp16.h>
#include <stdint.h>

// ============================================================================
// Problem constants / layout
// ============================================================================
#define D 128
#define TILE_M 64                 // persistent tile: 64 edges x 128 cols

#define ROW_BYTES  272            // padded fp16 row (136 halves): stride%128=16 -> ldmatrix conflict-free
#define STAGE_STRIDE 132          // fp32 stage row stride (528B: bank-rotating)

// SMEM layout (bytes):
//   [0, 17408)   A fp16 tile  (dead after MMA)
//   [0, 33792)   fp32 stage 64x132 (ALIASES A; written after MMA sync)
//   [33792]      bias (128 floats)
//   [34304]      dst slice (64 ints)
#define OFF_A      0
#define OFF_STAGE  0
#define OFF_BIAS   33792
#define OFF_DST    34304
#define SMEM_TOTAL 34560

// ============================================================================
// PTX helpers (base ISA only: ldmatrix / mma.sync)
// ============================================================================
__device__ __forceinline__ uint32_t smem_to_u32(const void* p) {
    uint32_t a;
    asm("{ .reg .u64 t; cvta.to.shared.u64 t, %1; cvt.u32.u64 %0, t; }" : "=r"(a) : "l"(p));
    return a;
}

#define LDSM4(r, addr) \
    asm volatile("ldmatrix.sync.aligned.m8n8.x4.shared.b16 {%0,%1,%2,%3}, [%4];" \
        : "=r"((r)[0]), "=r"((r)[1]), "=r"((r)[2]), "=r"((r)[3]) : "r"(addr))

#define MMA_F16(c, a, b0, b1) \
    asm volatile("mma.sync.aligned.m16n8k16.row.col.f32.f16.f16.f32 " \
        "{%0,%1,%2,%3},{%4,%5,%6,%7},{%8,%9},{%0,%1,%2,%3};" \
        : "+f"((c)[0]), "+f"((c)[1]), "+f"((c)[2]), "+f"((c)[3]) \
        : "r"((a)[0]), "r"((a)[1]), "r"((a)[2]), "r"((a)[3]), \
          "r"(b0), "r"(b1))

// ============================================================================
// W in B-fragment order: [kstep(8)][n8tile(16)][lane(32)] -> uint2 {b0, b1}
// Single fp16 table (measured rel_err 1.64e-4, 6x under threshold).
// ============================================================================
__device__ uint2 g_Wf[8 * 16 * 32];  // 32 KB, L1-resident

__device__ __forceinline__ uint32_t packf16(float x0, float x1) {
    __half h0 = __float2half_rn(x0);
    __half h1 = __float2half_rn(x1);
    return (uint32_t)__half_as_ushort(h0) | ((uint32_t)__half_as_ushort(h1) << 16);
}

// ============================================================================
// Kernel 0 (merged prep): init out to -inf AND pack W into fp16 fragments.
// ============================================================================
__global__ void prep_kernel(int4* __restrict__ out, int n4, const float* __restrict__ W) {
    const int init_blocks = (n4 + 255) / 256;
    if ((int)blockIdx.x < init_blocks) {
        int i = blockIdx.x * 256 + threadIdx.x;
        if (i < n4) {
            const int m = 0xff800000;  // -inf
            out[i] = make_int4(m, m, m, m);
        }
    } else {
        int i = (blockIdx.x - init_blocks) * 256 + threadIdx.x;  // 0 .. 4095
        if (i < 8 * 16 * 32) {
            int lane = i & 31;
            int n8t  = (i >> 5) & 15;
            int kst  = i >> 9;
            int n  = n8t * 8 + (lane >> 2);
            int k0 = kst * 16 + (lane & 3) * 2;
            const float* Wr = W + (size_t)n * D;
            g_Wf[i] = make_uint2(packf16(Wr[k0],     Wr[k0 + 1]),
                                 packf16(Wr[k0 + 8], Wr[k0 + 9]));
        }
    }
}

// ============================================================================
// Kernel 1: PERSISTENT fused GEMM + scatter-max, TILE_M=64, single MMA pass.
// Register-carried cross-tile prefetch (loads issued before MMA). Epilogue
// stages through SMEM so every atomicMax instruction is ONE dst row x 128B
// contiguous = 1 L1 wavefront (the R13/R14 direct-fragment scatter was ~8 wf).
// ============================================================================
__global__ __launch_bounds__(256, 2) void fused_kernel(
    const float* __restrict__ src,
    const float* __restrict__ b,
    const int* __restrict__ dst_idx,   // int32 (JAX x64-disabled downcasts int64)
    int* __restrict__ out,
    int E, int N, int tiles)
{
    extern __shared__ __align__(16) char smem[];
    float* bias_s = reinterpret_cast<float*>(smem + OFF_BIAS);
    int*   dst_s  = reinterpret_cast<int*>(smem + OFF_DST);

    const int tid  = threadIdx.x;
    const int wid  = tid >> 5;
    const int lane = tid & 31;

    const int m_base = (wid & 1) * 32;    // warp M tile (rows 0..63)
    const int n_base = (wid >> 1) * 32;   // warp N tile (cols 0..127)
    const int nb8    = n_base >> 3;       // first n8 tile index
    const int cb     = 2 * (lane & 3);

    if (tid < D) bias_s[tid] = b[tid];

    const uint32_t sb = smem_to_u32(smem);
    const uint32_t aBase = sb + OFF_A
        + (uint32_t)(m_base + (lane & 15)) * ROW_BYTES + (uint32_t)(lane >> 4) * 16;

    const float4* srcT = reinterpret_cast<const float4*>(src);
    const float4 z4 = make_float4(0.f, 0.f, 0.f, 0.f);

    // ---- initial prefetch: tile blockIdx.x (64 rows = 2048 float4) ----
    float4 pend[8];
    {
        int tb = blockIdx.x * TILE_M;
        int rm = min(TILE_M, E - tb);
        #pragma unroll
        for (int u = 0; u < 8; u++) {
            int i = tid + u * 256;           // 0..2047 -> row = i>>5 in 0..63
            pend[u] = ((i >> 5) < rm) ? __ldcs(&srcT[(size_t)tb * 32 + i]) : z4;
        }
    }

    for (int t = blockIdx.x; t < tiles; t += gridDim.x) {
        const int tile_base = t * TILE_M;
        const int rem = min(TILE_M, E - tile_base);

        __syncthreads();  // previous tile's stage fully scattered (region free)

        // ---- drain pending regs -> fp16 A tile in SMEM; load dst slice ----
        #pragma unroll
        for (int u = 0; u < 8; u++) {
            int i = tid + u * 256;
            int row = i >> 5;
            int col4 = i & 31;
            uint2 h = make_uint2(packf16(pend[u].x, pend[u].y),
                                 packf16(pend[u].z, pend[u].w));
            *reinterpret_cast<uint2*>(smem + OFF_A + (size_t)row * ROW_BYTES + (size_t)col4 * 8) = h;
        }
        if (tid < TILE_M) dst_s[tid] = (tid < rem) ? dst_idx[tile_base + tid] : -1;

        __syncthreads();  // A tile + dst_s ready

        // ---- issue next tile's loads NOW (complete during MMA below) ----
        {
            int tn = t + gridDim.x;
            if (tn < tiles) {
                int tbn = tn * TILE_M;
                int rmn = min(TILE_M, E - tbn);
                #pragma unroll
                for (int u = 0; u < 8; u++) {
                    int i = tid + u * 256;
                    pend[u] = ((i >> 5) < rmn) ? __ldcs(&srcT[(size_t)tbn * 32 + i]) : z4;
                }
            }
        }

        // ---- MMA: K=128 in 8 k16 steps; single pass (fp16 W), fp32 accum ----
        float acc[2][4][4];
        #pragma unroll
        for (int mt = 0; mt < 2; mt++)
            #pragma unroll
            for (int nt = 0; nt < 4; nt++)
                #pragma unroll
                for (int c = 0; c < 4; c++) acc[mt][nt][c] = 0.f;

        #pragma unroll
        for (int k = 0; k < 8; k++) {
            uint32_t a[2][4];
            #pragma unroll
            for (int mt = 0; mt < 2; mt++)
                LDSM4(a[mt], aBase + (uint32_t)mt * 16 * ROW_BYTES + (uint32_t)k * 32);
            const int fbase = (k * 16 + nb8) * 32 + lane;
            #pragma unroll
            for (int nt = 0; nt < 4; nt++) {
                const uint2 B = g_Wf[fbase + nt * 32];
                #pragma unroll
                for (int mt = 0; mt < 2; mt++)
                    MMA_F16(acc[mt][nt], a[mt], B.x, B.y);
            }
        }

        __syncthreads();  // all warps done reading A -> stage may overwrite it

        // ---- epilogue: bias + relu -> fp32 stage (row-major, coalescable) ----
        {
            float* stage = reinterpret_cast<float*>(smem + OFF_STAGE);
            const int r0 = m_base + (lane >> 2);
            #pragma unroll
            for (int mt = 0; mt < 2; mt++) {
                #pragma unroll
                for (int nt = 0; nt < 4; nt++) {
                    int col = n_base + nt * 8 + cb;
                    float bv0 = bias_s[col], bv1 = bias_s[col + 1];
                    int rr = r0 + mt * 16;
                    stage[rr * STAGE_STRIDE + col]           = fmaxf(acc[mt][nt][0] + bv0, 0.f);
                    stage[rr * STAGE_STRIDE + col + 1]       = fmaxf(acc[mt][nt][1] + bv1, 0.f);
                    stage[(rr + 8) * STAGE_STRIDE + col]     = fmaxf(acc[mt][nt][2] + bv0, 0.f);
                    stage[(rr + 8) * STAGE_STRIDE + col + 1] = fmaxf(acc[mt][nt][3] + bv1, 0.f);
                }
            }
        }
        __syncthreads();  // stage complete

        // ---- scatter: warp-per-row, 32 contiguous cols per atomic instr ----
        {
            const float* stage = reinterpret_cast<const float*>(smem + OFF_STAGE);
            for (int rr = wid; rr < rem; rr += 8) {
                int dst = dst_s[rr];
                if ((unsigned)dst >= (unsigned)N) continue;
                int* op = out + (size_t)dst * D;
                #pragma unroll
                for (int kk = 0; kk < 4; kk++) {
                    int col = lane + kk * 32;  // 128B contiguous = 1 wavefront
                    // relu => v >= 0; init 0xFF800000 => signed-int max == float max
                    atomicMax(op + col, __float_as_int(stage[rr * STAGE_STRIDE + col]));
                }
            }
        }
    }
}

// ============================================================================
// Launch
// ============================================================================
extern "C" void kernel_launch(void* const* d_in, const int* in_sizes, int n_in,
                              void* d_out, int out_size) {
    const float* src     = (const float*)d_in[0];
    const float* W       = (const float*)d_in[1];
    const float* b       = (const float*)d_in[2];
    const int*   dst     = (const int*)d_in[3];   // int32 on device

    const int E = in_sizes[0] / D;
    const int N = out_size / D;
    const int tiles = (E + TILE_M - 1) / TILE_M;

    // 0: merged prep (init out to -inf + pack W fp16 fragments)
    int n4 = out_size / 4;
    int init_blocks = (n4 + 255) / 256;
    int frag_blocks = (8 * 16 * 32 + 255) / 256;
    prep_kernel<<<init_blocks + frag_blocks, 256>>>((int4*)d_out, n4, W);

    // 1: persistent fused GEMM + scatter-max (2 CTAs/SM x 148 SMs)
    int grid = 296;
    if (grid > tiles) grid = tiles;
    cudaFuncSetAttribute(fused_kernel, cudaFuncAttributeMaxDynamicSharedMemorySize,
                         SMEM_TOTAL);
    fused_kernel<<<grid, 256, SMEM_TOTAL>>>(src, b, dst, (int*)d_out, E, N, tiles);
}

// round 16
// speedup vs baseline: 2.8437x; 1.0932x over previous
#include <cuda_runtime.h>
#include <cuda_fp16.h>
#include <stdint.h>

// ============================================================================
// Problem constants / layout
// ============================================================================
#define D 128
#define TILE_M 64                 // persistent tile: 64 edges x 128 cols

#define ROW_BYTES  272            // padded fp16 row: stride%128=16 -> ldmatrix conflict-free
#define STAGE_STRIDE 132          // fp32 stage row stride (528B: bank-rotating)

// SMEM layout (bytes), all regions DISTINCT (no aliasing):
//   [0, 32768)       fp32 cp.async landing buffer (64 x 128 floats)
//   [32768, 50176)   A fp16 tile (64 x 272B)
//   [50176, 83968)   fp32 stage 64 x 132
//   [83968]          bias (128 floats)
//   [84480]          dst slice (64 ints)
#define OFF_BUF    0
#define OFF_A      32768
#define OFF_STAGE  50176
#define OFF_BIAS   83968
#define OFF_DST    84480
#define SMEM_TOTAL 84736

// ============================================================================
// PTX helpers (base ISA only: ldmatrix / mma.sync / cp.async)
// ============================================================================
__device__ __forceinline__ uint32_t smem_to_u32(const void* p) {
    uint32_t a;
    asm("{ .reg .u64 t; cvta.to.shared.u64 t, %1; cvt.u32.u64 %0, t; }" : "=r"(a) : "l"(p));
    return a;
}

#define LDSM4(r, addr) \
    asm volatile("ldmatrix.sync.aligned.m8n8.x4.shared.b16 {%0,%1,%2,%3}, [%4];" \
        : "=r"((r)[0]), "=r"((r)[1]), "=r"((r)[2]), "=r"((r)[3]) : "r"(addr))

#define MMA_F16(c, a, b0, b1) \
    asm volatile("mma.sync.aligned.m16n8k16.row.col.f32.f16.f16.f32 " \
        "{%0,%1,%2,%3},{%4,%5,%6,%7},{%8,%9},{%0,%1,%2,%3};" \
        : "+f"((c)[0]), "+f"((c)[1]), "+f"((c)[2]), "+f"((c)[3]) \
        : "r"((a)[0]), "r"((a)[1]), "r"((a)[2]), "r"((a)[3]), \
          "r"(b0), "r"(b1))

#define CP_ASYNC_16(smem_addr, gmem_ptr, ssize) \
    asm volatile("cp.async.cg.shared.global [%0], [%1], 16, %2;" \
        :: "r"(smem_addr), "l"(gmem_ptr), "r"(ssize))

#define CP_ASYNC_COMMIT() asm volatile("cp.async.commit_group;" ::: "memory")
#define CP_ASYNC_WAIT0()  asm volatile("cp.async.wait_group 0;" ::: "memory")

// ============================================================================
// W in B-fragment order: [kstep(8)][n8tile(16)][lane(32)] -> uint2 {b0, b1}
// Single fp16 table (measured rel_err 1.64e-4). Each thread hoists its 32
// fragments (64 regs) ONCE per persistent CTA -> zero per-tile W L1 traffic.
// ============================================================================
__device__ uint2 g_Wf[8 * 16 * 32];  // 32 KB

__device__ __forceinline__ uint32_t packf16(float x0, float x1) {
    __half h0 = __float2half_rn(x0);
    __half h1 = __float2half_rn(x1);
    return (uint32_t)__half_as_ushort(h0) | ((uint32_t)__half_as_ushort(h1) << 16);
}

// ============================================================================
// Kernel 0 (merged prep): init out to -inf AND pack W into fp16 fragments.
// ============================================================================
__global__ void prep_kernel(int4* __restrict__ out, int n4, const float* __restrict__ W) {
    const int init_blocks = (n4 + 255) / 256;
    if ((int)blockIdx.x < init_blocks) {
        int i = blockIdx.x * 256 + threadIdx.x;
        if (i < n4) {
            const int m = 0xff800000;  // -inf
            out[i] = make_int4(m, m, m, m);
        }
    } else {
        int i = (blockIdx.x - init_blocks) * 256 + threadIdx.x;  // 0 .. 4095
        if (i < 8 * 16 * 32) {
            int lane = i & 31;
            int n8t  = (i >> 5) & 15;
            int kst  = i >> 9;
            int n  = n8t * 8 + (lane >> 2);
            int k0 = kst * 16 + (lane & 3) * 2;
            const float* Wr = W + (size_t)n * D;
            g_Wf[i] = make_uint2(packf16(Wr[k0],     Wr[k0 + 1]),
                                 packf16(Wr[k0 + 8], Wr[k0 + 9]));
        }
    }
}

// ============================================================================
// Kernel 1: PERSISTENT fused GEMM + scatter-max.
// - W fragments hoisted to registers once (no per-tile W L1 traffic).
// - Cross-tile src prefetch via cp.async into fp32 SMEM buffer (RF-bypassing).
//   Each thread cp.asyncs exactly the chunks it converts -> wait_group is
//   self-synchronizing per thread.
// - Staged scatter: every atomicMax instr = 1 dst row x 128B = 1 wavefront.
// ============================================================================
__global__ __launch_bounds__(256, 2) void fused_kernel(
    const float* __restrict__ src,
    const float* __restrict__ b,
    const int* __restrict__ dst_idx,   // int32 (JAX x64-disabled downcasts int64)
    int* __restrict__ out,
    int E, int N, int tiles)
{
    extern __shared__ __align__(16) char smem[];
    float* bias_s = reinterpret_cast<float*>(smem + OFF_BIAS);
    int*   dst_s  = reinterpret_cast<int*>(smem + OFF_DST);

    const int tid  = threadIdx.x;
    const int wid  = tid >> 5;
    const int lane = tid & 31;

    const int m_base = (wid & 1) * 32;    // warp M tile (rows 0..63)
    const int n_base = (wid >> 1) * 32;   // warp N tile (cols 0..127)
    const int nb8    = n_base >> 3;       // first n8 tile index
    const int cb     = 2 * (lane & 3);

    if (tid < D) bias_s[tid] = b[tid];

    // ---- hoist W fragments into registers (once per persistent CTA) ----
    uint2 Wr[8][4];
    #pragma unroll
    for (int k = 0; k < 8; k++)
        #pragma unroll
        for (int nt = 0; nt < 4; nt++)
            Wr[k][nt] = g_Wf[(k * 16 + nb8 + nt) * 32 + lane];

    const uint32_t sb = smem_to_u32(smem);
    const uint32_t aBase = sb + OFF_A
        + (uint32_t)(m_base + (lane & 15)) * ROW_BYTES + (uint32_t)(lane >> 4) * 16;

    const float4* srcT = reinterpret_cast<const float4*>(src);

    // ---- prologue: cp.async tile blockIdx.x into buf ----
    if (blockIdx.x < tiles) {
        int tb = blockIdx.x * TILE_M;
        int rm = min(TILE_M, E - tb);
        #pragma unroll
        for (int u = 0; u < 8; u++) {
            int i = tid + u * 256;           // 0..2047, row = i>>5
            int ssize = ((i >> 5) < rm) ? 16 : 0;
            CP_ASYNC_16(sb + OFF_BUF + (uint32_t)i * 16, srcT + (size_t)tb * 32 + i, ssize);
        }
    }
    CP_ASYNC_COMMIT();

    for (int t = blockIdx.x; t < tiles; t += gridDim.x) {
        const int tile_base = t * TILE_M;
        const int rem = min(TILE_M, E - tile_base);

        CP_ASYNC_WAIT0();     // this thread's buf chunks landed
        __syncthreads();      // all threads' chunks landed; prev stage scattered

        // ---- convert buf fp32 -> A fp16; load dst slice ----
        #pragma unroll
        for (int u = 0; u < 8; u++) {
            int i = tid + u * 256;
            int row = i >> 5;
            int col4 = i & 31;
            float4 x = *reinterpret_cast<const float4*>(smem + OFF_BUF + (size_t)i * 16);
            uint2 h = make_uint2(packf16(x.x, x.y), packf16(x.z, x.w));
            *reinterpret_cast<uint2*>(smem + OFF_A + (size_t)row * ROW_BYTES + (size_t)col4 * 8) = h;
        }
        if (tid < TILE_M) dst_s[tid] = (tid < rem) ? dst_idx[tile_base + tid] : -1;

        __syncthreads();      // A tile + dst_s ready; buf consumed

        // ---- issue next tile's cp.async NOW (completes during MMA+epilogue) ----
        {
            int tn = t + gridDim.x;
            if (tn < tiles) {
                int tbn = tn * TILE_M;
                int rmn = min(TILE_M, E - tbn);
                #pragma unroll
                for (int u = 0; u < 8; u++) {
                    int i = tid + u * 256;
                    int ssize = ((i >> 5) < rmn) ? 16 : 0;
                    CP_ASYNC_16(sb + OFF_BUF + (uint32_t)i * 16, srcT + (size_t)tbn * 32 + i, ssize);
                }
            }
            CP_ASYNC_COMMIT();
        }

        // ---- MMA: K=128 in 8 k16 steps; W from registers, fp32 accum ----
        float acc[2][4][4];
        #pragma unroll
        for (int mt = 0; mt < 2; mt++)
            #pragma unroll
            for (int nt = 0; nt < 4; nt++)
                #pragma unroll
                for (int c = 0; c < 4; c++) acc[mt][nt][c] = 0.f;

        #pragma unroll
        for (int k = 0; k < 8; k++) {
            uint32_t a[2][4];
            #pragma unroll
            for (int mt = 0; mt < 2; mt++)
                LDSM4(a[mt], aBase + (uint32_t)mt * 16 * ROW_BYTES + (uint32_t)k * 32);
            #pragma unroll
            for (int nt = 0; nt < 4; nt++)
                #pragma unroll
                for (int mt = 0; mt < 2; mt++)
                    MMA_F16(acc[mt][nt], a[mt], Wr[k][nt].x, Wr[k][nt].y);
        }

        // ---- epilogue: bias + relu -> fp32 stage (STS.64 pairs) ----
        {
            float* stage = reinterpret_cast<float*>(smem + OFF_STAGE);
            const int r0 = m_base + (lane >> 2);
            #pragma unroll
            for (int mt = 0; mt < 2; mt++) {
                #pragma unroll
                for (int nt = 0; nt < 4; nt++) {
                    int col = n_base + nt * 8 + cb;
                    float bv0 = bias_s[col], bv1 = bias_s[col + 1];
                    int rr = r0 + mt * 16;
                    *reinterpret_cast<float2*>(&stage[rr * STAGE_STRIDE + col]) =
                        make_float2(fmaxf(acc[mt][nt][0] + bv0, 0.f),
                                    fmaxf(acc[mt][nt][1] + bv1, 0.f));
                    *reinterpret_cast<float2*>(&stage[(rr + 8) * STAGE_STRIDE + col]) =
                        make_float2(fmaxf(acc[mt][nt][2] + bv0, 0.f),
                                    fmaxf(acc[mt][nt][3] + bv1, 0.f));
                }
            }
        }
        __syncthreads();      // stage complete (cross-warp rows)

        // ---- scatter: warp-per-row, 32 contiguous cols per atomic instr ----
        {
            const float* stage = reinterpret_cast<const float*>(smem + OFF_STAGE);
            for (int rr = wid; rr < rem; rr += 8) {
                int dst = dst_s[rr];
                if ((unsigned)dst >= (unsigned)N) continue;
                int* op = out + (size_t)dst * D;
                #pragma unroll
                for (int kk = 0; kk < 4; kk++) {
                    int col = lane + kk * 32;  // 128B contiguous = 1 wavefront
                    // relu => v >= 0; init 0xFF800000 => signed-int max == float max
                    atomicMax(op + col, __float_as_int(stage[rr * STAGE_STRIDE + col]));
                }
            }
        }
    }
}

// ============================================================================
// Launch
// ============================================================================
extern "C" void kernel_launch(void* const* d_in, const int* in_sizes, int n_in,
                              void* d_out, int out_size) {
    const float* src     = (const float*)d_in[0];
    const float* W       = (const float*)d_in[1];
    const float* b       = (const float*)d_in[2];
    const int*   dst     = (const int*)d_in[3];   // int32 on device

    const int E = in_sizes[0] / D;
    const int N = out_size / D;
    const int tiles = (E + TILE_M - 1) / TILE_M;

    // 0: merged prep (init out to -inf + pack W fp16 fragments)
    int n4 = out_size / 4;
    int init_blocks = (n4 + 255) / 256;
    int frag_blocks = (8 * 16 * 32 + 255) / 256;
    prep_kernel<<<init_blocks + frag_blocks, 256>>>((int4*)d_out, n4, W);

    // 1: persistent fused GEMM + scatter-max (2 CTAs/SM x 148 SMs)
    int grid = 296;
    if (grid > tiles) grid = tiles;
    cudaFuncSetAttribute(fused_kernel, cudaFuncAttributeMaxDynamicSharedMemorySize,
                         SMEM_TOTAL);
    fused_kernel<<<grid, 256, SMEM_TOTAL>>>(src, b, dst, (int*)d_out, E, N, tiles);
}